// round 8
// baseline (speedup 1.0000x reference)
#include <cuda_runtime.h>
#include <cstdint>

#define DIM 512
#define HEADS 8
#define HEAD_DIM 64
#define BATCH 2
#define SEQ 4096
#define M_TOT (BATCH*SEQ)           // 8192
#define ATTN_SCALE 0.125f           // 64^-0.5

// Scratch (allocation-free: device globals)
__device__ float g_q[BATCH*HEADS*SEQ*HEAD_DIM];
__device__ float g_k[BATCH*HEADS*SEQ*HEAD_DIM];
__device__ float g_v[BATCH*HEADS*SEQ*HEAD_DIM];
__device__ float g_attn[M_TOT*DIM];

// ---------------------------------------------------------------------------
// mma.sync m16n8k8 tf32 (baseline PTX) + helpers
// ---------------------------------------------------------------------------
__device__ __forceinline__ void mma_tf32(float* d, const uint32_t* a,
                                         uint32_t b0, uint32_t b1) {
    asm volatile(
        "mma.sync.aligned.m16n8k8.row.col.f32.tf32.tf32.f32 "
        "{%0,%1,%2,%3}, {%4,%5,%6,%7}, {%8,%9}, {%0,%1,%2,%3};"
        : "+f"(d[0]), "+f"(d[1]), "+f"(d[2]), "+f"(d[3])
        : "r"(a[0]), "r"(a[1]), "r"(a[2]), "r"(a[3]), "r"(b0), "r"(b1));
}

__device__ __forceinline__ uint32_t f2tf32(float x) {
    uint32_t r;
    asm("cvt.rna.tf32.f32 %0, %1;" : "=r"(r) : "f"(x));
    return r;
}

__device__ __forceinline__ uint32_t smem_u32(const void* p) {
    uint32_t a;
    asm("{ .reg .u64 t; cvta.to.shared.u64 t, %1; cvt.u32.u64 %0, t; }"
        : "=r"(a) : "l"(p));
    return a;
}

#define CP_ASYNC16(dst, src) \
    asm volatile("cp.async.cg.shared.global [%0], [%1], 16;" \
                 :: "r"(dst), "l"(src) : "memory")
#define CP_COMMIT() asm volatile("cp.async.commit_group;" ::: "memory")
#define CP_WAIT0()  asm volatile("cp.async.wait_group 0;" ::: "memory")
#define CP_WAIT1()  asm volatile("cp.async.wait_group 1;" ::: "memory")

// ===========================================================================
// Split-precision tf32 tensor GEMM, hi/lo computed at staging time.
// CTA 128x128, BK=16, 256 threads (8 warps 2m x 4n, warp tile 64x32).
// ===========================================================================
#define GP 20
#define GST (128 * GP)                 // 2560 u32 per stage-buffer
#define GEMM_SMEM (8 * GST * 4)        // 81,920 B

#define SPLIT_STORE(BH, BL, off, v) do {                                     \
    uint4 _h, _l;                                                            \
    _h.x = f2tf32((v).x); _l.x = f2tf32((v).x - __uint_as_float(_h.x));      \
    _h.y = f2tf32((v).y); _l.y = f2tf32((v).y - __uint_as_float(_h.y));      \
    _h.z = f2tf32((v).z); _l.z = f2tf32((v).z - __uint_as_float(_h.z));      \
    _h.w = f2tf32((v).w); _l.w = f2tf32((v).w - __uint_as_float(_h.w));      \
    *(uint4*)((BH) + (off)) = _h;                                            \
    *(uint4*)((BL) + (off)) = _l;                                            \
} while (0)

#define GEMM_BODY(Aptr, Wptr)                                                \
    extern __shared__ uint32_t gsm[];                                        \
    uint32_t* Ah = gsm;                                                      \
    uint32_t* Al = gsm + 2 * GST;                                            \
    uint32_t* Wh = gsm + 4 * GST;                                            \
    uint32_t* Wl = gsm + 6 * GST;                                            \
    const int tid  = threadIdx.x;                                            \
    const int m0   = blockIdx.y * 128;                                       \
    const int n0   = blockIdx.x * 128;                                       \
    const int wid  = tid >> 5, lane = tid & 31;                              \
    const int qp   = lane >> 2, c = lane & 3;                                \
    const int wm   = (wid >> 2) * 64;                                        \
    const int wn   = (wid & 3) * 32;                                         \
    float C[16][4];                                                          \
    _Pragma("unroll")                                                        \
    for (int t = 0; t < 16; t++)                                             \
        { C[t][0] = 0.f; C[t][1] = 0.f; C[t][2] = 0.f; C[t][3] = 0.f; }      \
    const int srow0 = tid >> 2, sc4 = (tid & 3) * 4;                         \
    const int srow1 = srow0 + 64;                                            \
    {                                                                        \
        float4 a0 = *(const float4*)(Aptr + (size_t)(m0 + srow0) * DIM + sc4); \
        float4 a1 = *(const float4*)(Aptr + (size_t)(m0 + srow1) * DIM + sc4); \
        float4 w0 = *(const float4*)(Wptr + (size_t)(n0 + srow0) * DIM + sc4); \
        float4 w1 = *(const float4*)(Wptr + (size_t)(n0 + srow1) * DIM + sc4); \
        SPLIT_STORE(Ah, Al, srow0 * GP + sc4, a0);                           \
        SPLIT_STORE(Ah, Al, srow1 * GP + sc4, a1);                           \
        SPLIT_STORE(Wh, Wl, srow0 * GP + sc4, w0);                           \
        SPLIT_STORE(Wh, Wl, srow1 * GP + sc4, w1);                           \
    }                                                                        \
    __syncthreads();                                                         \
    for (int s = 0; s < DIM / 16; s++) {                                     \
        const int cur = (s & 1) * GST;                                       \
        float4 pa0, pa1, pw0, pw1;                                           \
        if (s < DIM / 16 - 1) {                                              \
            int nk = (s + 1) * 16;                                           \
            pa0 = *(const float4*)(Aptr + (size_t)(m0 + srow0) * DIM + nk + sc4); \
            pa1 = *(const float4*)(Aptr + (size_t)(m0 + srow1) * DIM + nk + sc4); \
            pw0 = *(const float4*)(Wptr + (size_t)(n0 + srow0) * DIM + nk + sc4); \
            pw1 = *(const float4*)(Wptr + (size_t)(n0 + srow1) * DIM + nk + sc4); \
        }                                                                    \
        _Pragma("unroll")                                                    \
        for (int kk = 0; kk < 2; kk++) {                                     \
            uint32_t ahi[16], alo[16], bhi[8], blo[8];                       \
            _Pragma("unroll")                                                \
            for (int mt = 0; mt < 4; mt++) {                                 \
                int off = cur + (wm + mt * 16 + qp) * GP + kk * 8 + c;       \
                ahi[mt*4+0] = Ah[off];                                       \
                ahi[mt*4+1] = Ah[off + 8 * GP];                              \
                ahi[mt*4+2] = Ah[off + 4];                                   \
                ahi[mt*4+3] = Ah[off + 8 * GP + 4];                          \
                alo[mt*4+0] = Al[off];                                       \
                alo[mt*4+1] = Al[off + 8 * GP];                              \
                alo[mt*4+2] = Al[off + 4];                                   \
                alo[mt*4+3] = Al[off + 8 * GP + 4];                          \
            }                                                                \
            _Pragma("unroll")                                                \
            for (int nt = 0; nt < 4; nt++) {                                 \
                int off = cur + (wn + nt * 8 + qp) * GP + kk * 8 + c;        \
                bhi[nt*2+0] = Wh[off];                                       \
                bhi[nt*2+1] = Wh[off + 4];                                   \
                blo[nt*2+0] = Wl[off];                                       \
                blo[nt*2+1] = Wl[off + 4];                                   \
            }                                                                \
            _Pragma("unroll")                                                \
            for (int mt = 0; mt < 4; mt++)                                   \
                _Pragma("unroll")                                            \
                for (int nt = 0; nt < 4; nt++) {                             \
                    mma_tf32(C[mt*4+nt], ahi + mt*4, bhi[nt*2], bhi[nt*2+1]); \
                    mma_tf32(C[mt*4+nt], ahi + mt*4, blo[nt*2], blo[nt*2+1]); \
                    mma_tf32(C[mt*4+nt], alo + mt*4, bhi[nt*2], bhi[nt*2+1]); \
                }                                                            \
        }                                                                    \
        if (s < DIM / 16 - 1) {                                              \
            const int nb = ((s + 1) & 1) * GST;                              \
            SPLIT_STORE(Ah + nb, Al + nb, srow0 * GP + sc4, pa0);            \
            SPLIT_STORE(Ah + nb, Al + nb, srow1 * GP + sc4, pa1);            \
            SPLIT_STORE(Wh + nb, Wl + nb, srow0 * GP + sc4, pw0);            \
            SPLIT_STORE(Wh + nb, Wl + nb, srow1 * GP + sc4, pw1);            \
        }                                                                    \
        __syncthreads();                                                     \
    }

__global__ __launch_bounds__(256) void qkv_gemm_tc(const float* __restrict__ A,
                                                   const float* __restrict__ W,
                                                   const float* __restrict__ bias) {
    GEMM_BODY(A, W)
    // Epilogue: bias add + scatter. K and V are pre-rounded to tf32 (rna)
    // so flash can consume raw bits (HW rz-truncation becomes identity).
#pragma unroll
    for (int mt = 0; mt < 4; mt++) {
#pragma unroll
        for (int nt = 0; nt < 4; nt++) {
#pragma unroll
            for (int half = 0; half < 2; half++) {
                int m  = m0 + wm + mt * 16 + qp + half * 8;
                int b  = m >> 12;
                int nn = m & 4095;
                int n  = n0 + wn + nt * 8 + c * 2;
                float v0 = C[mt*4+nt][half*2+0] + bias[n];
                float v1 = C[mt*4+nt][half*2+1] + bias[n + 1];
                int which = n >> 9;
                int cc = n & 511;
                int h  = cc >> 6;
                int d  = cc & 63;
                int bhh = b * HEADS + h;
                if (which != 0) {
                    v0 = __uint_as_float(f2tf32(v0));
                    v1 = __uint_as_float(f2tf32(v1));
                }
                float* dst = (which == 0) ? g_q : ((which == 1) ? g_k : g_v);
                *(float2*)(dst + ((size_t)bhh * SEQ + nn) * HEAD_DIM + d) =
                    make_float2(v0, v1);
            }
        }
    }
}

__global__ __launch_bounds__(256) void proj_gemm_tc(const float* __restrict__ W,
                                                    const float* __restrict__ bias,
                                                    float* __restrict__ out) {
    const float* Ain = g_attn;
    GEMM_BODY(Ain, W)
#pragma unroll
    for (int mt = 0; mt < 4; mt++) {
#pragma unroll
        for (int nt = 0; nt < 4; nt++) {
#pragma unroll
            for (int half = 0; half < 2; half++) {
                int m = m0 + wm + mt * 16 + qp + half * 8;
                int n = n0 + wn + nt * 8 + c * 2;
                float v0 = C[mt*4+nt][half*2+0] + bias[n];
                float v1 = C[mt*4+nt][half*2+1] + bias[n + 1];
                *(float2*)(out + (size_t)m * DIM + n) = make_float2(v0, v1);
            }
        }
    }
}

// ===========================================================================
// Flash attention: 64-row CTAs (4 warps), 3 CTAs/SM, 64-key tiles,
// DOUBLE-BUFFERED cp.async pipeline (prefetch kt+1 during compute of kt).
// K/V already tf32-rounded in gmem; Q rounded (rna) at staging.
// ===========================================================================
#define FPITCH 68
#define FSTAGE (64 * FPITCH)               // u32 per 64-row stage
#define FLASH_SMEM (4 * FSTAGE * 4)        // K0,K1,V0,V1 = 69,632 B
#define NKT (SEQ / 64)                     // 64 key tiles

__global__ __launch_bounds__(128, 3) void flash_attn_mma() {
    extern __shared__ uint32_t sbuf[];
    // layout: K stage0, K stage1, V stage0, V stage1
    uint32_t* bufK[2] = { sbuf,              sbuf + FSTAGE };
    uint32_t* bufV[2] = { sbuf + 2 * FSTAGE, sbuf + 3 * FSTAGE };
    const uint32_t skb0 = smem_u32(bufK[0]);

    const int tid  = threadIdx.x;
    const int wid  = tid >> 5;             // 0..3
    const int lane = tid & 31;
    const int qp   = lane >> 2;
    const int c    = lane & 3;

    const int bh = blockIdx.x >> 6;        // 0..15
    const int qt = blockIdx.x & 63;        // 64-row query tile

    const float* qbase = g_q + ((size_t)bh * SEQ + (size_t)qt * 64) * HEAD_DIM;
    const float* kbase = g_k + (size_t)bh * SEQ * HEAD_DIM;
    const float* vbase = g_v + (size_t)bh * SEQ * HEAD_DIM;

    // ---- Stage Q (scaled, rna) into K-stage0, extract A-fragments ----
#pragma unroll
    for (int i = 0; i < 8; i++) {
        int idx = tid + i * 128;           // 0..1023
        int row = idx >> 4, c4 = (idx & 15) * 4;
        float4 v = *(const float4*)(qbase + (size_t)row * HEAD_DIM + c4);
        uint4 u;
        u.x = f2tf32(v.x * ATTN_SCALE); u.y = f2tf32(v.y * ATTN_SCALE);
        u.z = f2tf32(v.z * ATTN_SCALE); u.w = f2tf32(v.w * ATTN_SCALE);
        *(uint4*)(bufK[0] + row * FPITCH + c4) = u;
    }
    __syncthreads();

    uint32_t qa[32];
#pragma unroll
    for (int ks = 0; ks < 8; ks++) {
        const uint32_t* qlo = bufK[0] + (wid * 16 + qp) * FPITCH + ks * 8 + c;
        const uint32_t* qhi = qlo + 8 * FPITCH;
        qa[ks*4+0] = qlo[0];
        qa[ks*4+1] = qhi[0];
        qa[ks*4+2] = qlo[4];
        qa[ks*4+3] = qhi[4];
    }
    __syncthreads();

    float oc[8][4];
#pragma unroll
    for (int t = 0; t < 8; t++)
#pragma unroll
        for (int r = 0; r < 4; r++) oc[t][r] = 0.f;
    float m_lo = -1e30f, m_hi = -1e30f;
    float l_lo = 0.f,    l_hi = 0.f;

    const int stg_row = tid >> 4;          // 0..7 base row
    const int stg_c4  = (tid & 15) * 4;

    // ---- Prologue: stage kt=0 into stage 0 ----
    {
        uint32_t kd = smem_u32(bufK[0]);
        uint32_t vd = smem_u32(bufV[0]);
#pragma unroll
        for (int i = 0; i < 8; i++) {
            int row = stg_row + i * 8;
            uint32_t soff = (uint32_t)(row * FPITCH + stg_c4) * 4u;
            CP_ASYNC16(kd + soff, kbase + (size_t)row * HEAD_DIM + stg_c4);
            CP_ASYNC16(vd + soff, vbase + (size_t)row * HEAD_DIM + stg_c4);
        }
        CP_COMMIT();
    }

    for (int kt = 0; kt < NKT; kt++) {
        const int cur = kt & 1;

        // ---- Prefetch kt+1 into the other stage ----
        if (kt + 1 < NKT) {
            uint32_t kd = smem_u32(bufK[cur ^ 1]);
            uint32_t vd = smem_u32(bufV[cur ^ 1]);
            const float* gk = kbase + (size_t)(kt + 1) * 64 * HEAD_DIM;
            const float* gv = vbase + (size_t)(kt + 1) * 64 * HEAD_DIM;
#pragma unroll
            for (int i = 0; i < 8; i++) {
                int row = stg_row + i * 8;
                uint32_t soff = (uint32_t)(row * FPITCH + stg_c4) * 4u;
                CP_ASYNC16(kd + soff, gk + (size_t)row * HEAD_DIM + stg_c4);
                CP_ASYNC16(vd + soff, gv + (size_t)row * HEAD_DIM + stg_c4);
            }
            CP_COMMIT();
            CP_WAIT1();
        } else {
            CP_WAIT0();
        }
        __syncthreads();

        const uint32_t* Kt = bufK[cur];
        const uint32_t* Vt = bufV[cur];

        // ---- S = Q @ K^T : 8 n-tiles x 8 k-steps ----
        float sc[8][4];
#pragma unroll
        for (int t = 0; t < 8; t++)
#pragma unroll
            for (int r = 0; r < 4; r++) sc[t][r] = 0.f;

#pragma unroll
        for (int nt = 0; nt < 8; nt++) {
            const uint32_t* kr = Kt + (nt * 8 + qp) * FPITCH + c;
#pragma unroll
            for (int ks = 0; ks < 8; ks++) {
                uint32_t b0 = kr[ks * 8];
                uint32_t b1 = kr[ks * 8 + 4];
                mma_tf32(sc[nt], qa + ks * 4, b0, b1);
            }
        }

        // ---- Online softmax ----
        float mx_lo = -1e30f, mx_hi = -1e30f;
#pragma unroll
        for (int t = 0; t < 8; t++) {
            mx_lo = fmaxf(mx_lo, fmaxf(sc[t][0], sc[t][1]));
            mx_hi = fmaxf(mx_hi, fmaxf(sc[t][2], sc[t][3]));
        }
        mx_lo = fmaxf(mx_lo, __shfl_xor_sync(0xffffffffu, mx_lo, 1));
        mx_lo = fmaxf(mx_lo, __shfl_xor_sync(0xffffffffu, mx_lo, 2));
        mx_hi = fmaxf(mx_hi, __shfl_xor_sync(0xffffffffu, mx_hi, 1));
        mx_hi = fmaxf(mx_hi, __shfl_xor_sync(0xffffffffu, mx_hi, 2));

        float mn_lo = fmaxf(m_lo, mx_lo);
        float mn_hi = fmaxf(m_hi, mx_hi);
        float al_lo = __expf(m_lo - mn_lo);
        float al_hi = __expf(m_hi - mn_hi);
        m_lo = mn_lo; m_hi = mn_hi;

        float s_lo = 0.f, s_hi = 0.f;
#pragma unroll
        for (int t = 0; t < 8; t++) {
            sc[t][0] = __expf(sc[t][0] - mn_lo);
            sc[t][1] = __expf(sc[t][1] - mn_lo);
            sc[t][2] = __expf(sc[t][2] - mn_hi);
            sc[t][3] = __expf(sc[t][3] - mn_hi);
            s_lo += sc[t][0] + sc[t][1];
            s_hi += sc[t][2] + sc[t][3];
        }
        l_lo = al_lo * l_lo + s_lo;
        l_hi = al_hi * l_hi + s_hi;

#pragma unroll
        for (int t = 0; t < 8; t++) {
            oc[t][0] *= al_lo; oc[t][1] *= al_lo;
            oc[t][2] *= al_hi; oc[t][3] *= al_hi;
        }

        // ---- O += P @ V : 8 key-octet k-steps ----
#pragma unroll
        for (int ks = 0; ks < 8; ks++) {
            int s0 = c >> 1;
            int s1 = 2 + (c >> 1);
            float t0 = __shfl_sync(0xffffffffu, sc[ks][0], s0, 4);
            float t1 = __shfl_sync(0xffffffffu, sc[ks][1], s0, 4);
            float t2 = __shfl_sync(0xffffffffu, sc[ks][2], s0, 4);
            float t3 = __shfl_sync(0xffffffffu, sc[ks][3], s0, 4);
            float u0 = __shfl_sync(0xffffffffu, sc[ks][0], s1, 4);
            float u1 = __shfl_sync(0xffffffffu, sc[ks][1], s1, 4);
            float u2 = __shfl_sync(0xffffffffu, sc[ks][2], s1, 4);
            float u3 = __shfl_sync(0xffffffffu, sc[ks][3], s1, 4);
            uint32_t a[4];
            a[0] = __float_as_uint((c & 1) ? t1 : t0);
            a[1] = __float_as_uint((c & 1) ? t3 : t2);
            a[2] = __float_as_uint((c & 1) ? u1 : u0);
            a[3] = __float_as_uint((c & 1) ? u3 : u2);

            const uint32_t* vr = Vt + (ks * 8 + c) * FPITCH + qp;
#pragma unroll
            for (int nt = 0; nt < 8; nt++) {
                uint32_t b0 = vr[nt * 8];
                uint32_t b1 = vr[4 * FPITCH + nt * 8];
                mma_tf32(oc[nt], a, b0, b1);
            }
        }
        __syncthreads();
    }

    // ---- Final: reduce l across quad, normalize, write ----
    l_lo += __shfl_xor_sync(0xffffffffu, l_lo, 1);
    l_lo += __shfl_xor_sync(0xffffffffu, l_lo, 2);
    l_hi += __shfl_xor_sync(0xffffffffu, l_hi, 1);
    l_hi += __shfl_xor_sync(0xffffffffu, l_hi, 2);
    const float inv_lo = 1.f / l_lo;
    const float inv_hi = 1.f / l_hi;

    const int b = bh >> 3, h = bh & 7;
    const int n_lo = qt * 64 + wid * 16 + qp;
    const int n_hi = n_lo + 8;
    float* olo = g_attn + (((size_t)b * SEQ + n_lo) * HEADS + h) * HEAD_DIM;
    float* ohi = g_attn + (((size_t)b * SEQ + n_hi) * HEADS + h) * HEAD_DIM;
#pragma unroll
    for (int t = 0; t < 8; t++) {
        int d = t * 8 + c * 2;
        *(float2*)(olo + d) = make_float2(oc[t][0] * inv_lo, oc[t][1] * inv_lo);
        *(float2*)(ohi + d) = make_float2(oc[t][2] * inv_hi, oc[t][3] * inv_hi);
    }
    (void)skb0;
}

// ---------------------------------------------------------------------------

extern "C" void kernel_launch(void* const* d_in, const int* in_sizes, int n_in,
                              void* d_out, int out_size) {
    const float* x      = (const float*)d_in[0];
    const float* qkv_w  = (const float*)d_in[1];
    const float* qkv_b  = (const float*)d_in[2];
    const float* proj_w = (const float*)d_in[3];
    const float* proj_b = (const float*)d_in[4];
    float* out = (float*)d_out;

    cudaFuncSetAttribute(qkv_gemm_tc,
                         cudaFuncAttributeMaxDynamicSharedMemorySize, GEMM_SMEM);
    cudaFuncSetAttribute(proj_gemm_tc,
                         cudaFuncAttributeMaxDynamicSharedMemorySize, GEMM_SMEM);
    cudaFuncSetAttribute(flash_attn_mma,
                         cudaFuncAttributeMaxDynamicSharedMemorySize, FLASH_SMEM);

    qkv_gemm_tc<<<dim3(12, 64), 256, GEMM_SMEM>>>(x, qkv_w, qkv_b);
    flash_attn_mma<<<16 * (SEQ / 64), 128, FLASH_SMEM>>>();
    proj_gemm_tc<<<dim3(4, 64), 256, GEMM_SMEM>>>(proj_w, proj_b, out);
}

// round 9
// speedup vs baseline: 1.6638x; 1.6638x over previous
#include <cuda_runtime.h>
#include <cstdint>

#define DIM 512
#define HEADS 8
#define HEAD_DIM 64
#define BATCH 2
#define SEQ 4096
#define M_TOT (BATCH*SEQ)           // 8192
#define ATTN_SCALE 0.125f           // 64^-0.5

// Scratch (allocation-free: device globals)
__device__ float g_q[BATCH*HEADS*SEQ*HEAD_DIM];
__device__ float g_k[BATCH*HEADS*SEQ*HEAD_DIM];
__device__ float g_v[BATCH*HEADS*SEQ*HEAD_DIM];
__device__ float g_attn[M_TOT*DIM];

// ---------------------------------------------------------------------------
// mma.sync m16n8k8 tf32 (baseline PTX) + helpers
// ---------------------------------------------------------------------------
__device__ __forceinline__ void mma_tf32(float* d, const uint32_t* a,
                                         uint32_t b0, uint32_t b1) {
    asm volatile(
        "mma.sync.aligned.m16n8k8.row.col.f32.tf32.tf32.f32 "
        "{%0,%1,%2,%3}, {%4,%5,%6,%7}, {%8,%9}, {%0,%1,%2,%3};"
        : "+f"(d[0]), "+f"(d[1]), "+f"(d[2]), "+f"(d[3])
        : "r"(a[0]), "r"(a[1]), "r"(a[2]), "r"(a[3]), "r"(b0), "r"(b1));
}

__device__ __forceinline__ uint32_t f2tf32(float x) {
    uint32_t r;
    asm("cvt.rna.tf32.f32 %0, %1;" : "=r"(r) : "f"(x));
    return r;
}

__device__ __forceinline__ uint32_t smem_u32(const void* p) {
    uint32_t a;
    asm("{ .reg .u64 t; cvta.to.shared.u64 t, %1; cvt.u32.u64 %0, t; }"
        : "=r"(a) : "l"(p));
    return a;
}

#define CP_ASYNC16(dst, src) \
    asm volatile("cp.async.cg.shared.global [%0], [%1], 16;" \
                 :: "r"(dst), "l"(src) : "memory")
#define CP_COMMIT() asm volatile("cp.async.commit_group;" ::: "memory")
#define CP_WAIT0()  asm volatile("cp.async.wait_group 0;" ::: "memory")

// ===========================================================================
// Split-precision tf32 tensor GEMM, hi/lo computed at staging time.
// CTA 128x128, BK=16, 256 threads (8 warps 2m x 4n, warp tile 64x32).
// Fragment loads PHASED to cut register liveness; 2 CTAs/SM forced.
// ===========================================================================
#define GP 20
#define GST (128 * GP)                 // 2560 u32 per stage-buffer
#define GEMM_SMEM (8 * GST * 4)        // 81,920 B

#define SPLIT_STORE(BH, BL, off, v) do {                                     \
    uint4 _h, _l;                                                            \
    _h.x = f2tf32((v).x); _l.x = f2tf32((v).x - __uint_as_float(_h.x));      \
    _h.y = f2tf32((v).y); _l.y = f2tf32((v).y - __uint_as_float(_h.y));      \
    _h.z = f2tf32((v).z); _l.z = f2tf32((v).z - __uint_as_float(_h.z));      \
    _h.w = f2tf32((v).w); _l.w = f2tf32((v).w - __uint_as_float(_h.w));      \
    *(uint4*)((BH) + (off)) = _h;                                            \
    *(uint4*)((BL) + (off)) = _l;                                            \
} while (0)

#define LOAD_AFRAG(dst, BUF, off)                                            \
    _Pragma("unroll")                                                        \
    for (int mt = 0; mt < 4; mt++) {                                         \
        int _o = (off) + mt * 16 * GP;                                       \
        (dst)[mt*4+0] = (BUF)[_o];                                           \
        (dst)[mt*4+1] = (BUF)[_o + 8 * GP];                                  \
        (dst)[mt*4+2] = (BUF)[_o + 4];                                       \
        (dst)[mt*4+3] = (BUF)[_o + 8 * GP + 4];                              \
    }
#define LOAD_BFRAG(dst, BUF, off)                                            \
    _Pragma("unroll")                                                        \
    for (int nt = 0; nt < 4; nt++) {                                         \
        int _o = (off) + nt * 8 * GP;                                        \
        (dst)[nt*2+0] = (BUF)[_o];                                           \
        (dst)[nt*2+1] = (BUF)[_o + 4];                                       \
    }
#define MMA_PASS(AF, BF)                                                     \
    _Pragma("unroll")                                                        \
    for (int mt = 0; mt < 4; mt++)                                           \
        _Pragma("unroll")                                                    \
        for (int nt = 0; nt < 4; nt++)                                       \
            mma_tf32(C[mt*4+nt], (AF) + mt*4, (BF)[nt*2], (BF)[nt*2+1]);

#define GEMM_BODY(Aptr, Wptr)                                                \
    extern __shared__ uint32_t gsm[];                                        \
    uint32_t* Ah = gsm;                                                      \
    uint32_t* Al = gsm + 2 * GST;                                            \
    uint32_t* Wh = gsm + 4 * GST;                                            \
    uint32_t* Wl = gsm + 6 * GST;                                            \
    const int tid  = threadIdx.x;                                            \
    const int m0   = blockIdx.y * 128;                                       \
    const int n0   = blockIdx.x * 128;                                       \
    const int wid  = tid >> 5, lane = tid & 31;                              \
    const int qp   = lane >> 2, c = lane & 3;                                \
    const int wm   = (wid >> 2) * 64;                                        \
    const int wn   = (wid & 3) * 32;                                         \
    float C[16][4];                                                          \
    _Pragma("unroll")                                                        \
    for (int t = 0; t < 16; t++)                                             \
        { C[t][0] = 0.f; C[t][1] = 0.f; C[t][2] = 0.f; C[t][3] = 0.f; }      \
    const int srow0 = tid >> 2, sc4 = (tid & 3) * 4;                         \
    const int srow1 = srow0 + 64;                                            \
    {                                                                        \
        float4 a0 = *(const float4*)(Aptr + (size_t)(m0 + srow0) * DIM + sc4); \
        float4 a1 = *(const float4*)(Aptr + (size_t)(m0 + srow1) * DIM + sc4); \
        float4 w0 = *(const float4*)(Wptr + (size_t)(n0 + srow0) * DIM + sc4); \
        float4 w1 = *(const float4*)(Wptr + (size_t)(n0 + srow1) * DIM + sc4); \
        SPLIT_STORE(Ah, Al, srow0 * GP + sc4, a0);                           \
        SPLIT_STORE(Ah, Al, srow1 * GP + sc4, a1);                           \
        SPLIT_STORE(Wh, Wl, srow0 * GP + sc4, w0);                           \
        SPLIT_STORE(Wh, Wl, srow1 * GP + sc4, w1);                           \
    }                                                                        \
    __syncthreads();                                                         \
    for (int s = 0; s < DIM / 16; s++) {                                     \
        const int cur = (s & 1) * GST;                                       \
        float4 pa0, pa1, pw0, pw1;                                           \
        if (s < DIM / 16 - 1) {                                              \
            int nk = (s + 1) * 16;                                           \
            pa0 = *(const float4*)(Aptr + (size_t)(m0 + srow0) * DIM + nk + sc4); \
            pa1 = *(const float4*)(Aptr + (size_t)(m0 + srow1) * DIM + nk + sc4); \
            pw0 = *(const float4*)(Wptr + (size_t)(n0 + srow0) * DIM + nk + sc4); \
            pw1 = *(const float4*)(Wptr + (size_t)(n0 + srow1) * DIM + nk + sc4); \
        }                                                                    \
        _Pragma("unroll")                                                    \
        for (int kk = 0; kk < 2; kk++) {                                     \
            const int aoff = cur + (wm + qp) * GP + kk * 8 + c;              \
            const int boff = cur + (wn + qp) * GP + kk * 8 + c;              \
            uint32_t af[16], bf[8];                                          \
            LOAD_AFRAG(af, Ah, aoff)      /* ahi */                          \
            LOAD_BFRAG(bf, Wh, boff)      /* bhi */                          \
            MMA_PASS(af, bf)              /* hi*hi */                        \
            {                                                                \
                uint32_t bl[8];                                              \
                LOAD_BFRAG(bl, Wl, boff)  /* blo */                          \
                MMA_PASS(af, bl)          /* hi*lo */                        \
            }                                                                \
            LOAD_AFRAG(af, Al, aoff)      /* alo (overwrites ahi) */         \
            MMA_PASS(af, bf)              /* lo*hi */                        \
        }                                                                    \
        if (s < DIM / 16 - 1) {                                              \
            const int nb = ((s + 1) & 1) * GST;                              \
            SPLIT_STORE(Ah + nb, Al + nb, srow0 * GP + sc4, pa0);            \
            SPLIT_STORE(Ah + nb, Al + nb, srow1 * GP + sc4, pa1);            \
            SPLIT_STORE(Wh + nb, Wl + nb, srow0 * GP + sc4, pw0);            \
            SPLIT_STORE(Wh + nb, Wl + nb, srow1 * GP + sc4, pw1);            \
        }                                                                    \
        __syncthreads();                                                     \
    }

__global__ __launch_bounds__(256, 2) void qkv_gemm_tc(const float* __restrict__ A,
                                                      const float* __restrict__ W,
                                                      const float* __restrict__ bias) {
    GEMM_BODY(A, W)
    // Epilogue: bias add + scatter. K and V pre-rounded to tf32 (rna) so
    // flash can consume raw bits (HW rz-truncation becomes identity).
#pragma unroll
    for (int mt = 0; mt < 4; mt++) {
#pragma unroll
        for (int nt = 0; nt < 4; nt++) {
#pragma unroll
            for (int half = 0; half < 2; half++) {
                int m  = m0 + wm + mt * 16 + qp + half * 8;
                int b  = m >> 12;
                int nn = m & 4095;
                int n  = n0 + wn + nt * 8 + c * 2;
                float v0 = C[mt*4+nt][half*2+0] + bias[n];
                float v1 = C[mt*4+nt][half*2+1] + bias[n + 1];
                int which = n >> 9;
                int cc = n & 511;
                int h  = cc >> 6;
                int d  = cc & 63;
                int bhh = b * HEADS + h;
                if (which != 0) {
                    v0 = __uint_as_float(f2tf32(v0));
                    v1 = __uint_as_float(f2tf32(v1));
                }
                float* dst = (which == 0) ? g_q : ((which == 1) ? g_k : g_v);
                *(float2*)(dst + ((size_t)bhh * SEQ + nn) * HEAD_DIM + d) =
                    make_float2(v0, v1);
            }
        }
    }
}

__global__ __launch_bounds__(256, 2) void proj_gemm_tc(const float* __restrict__ W,
                                                       const float* __restrict__ bias,
                                                       float* __restrict__ out) {
    const float* Ain = g_attn;
    GEMM_BODY(Ain, W)
#pragma unroll
    for (int mt = 0; mt < 4; mt++) {
#pragma unroll
        for (int nt = 0; nt < 4; nt++) {
#pragma unroll
            for (int half = 0; half < 2; half++) {
                int m = m0 + wm + mt * 16 + qp + half * 8;
                int n = n0 + wn + nt * 8 + c * 2;
                float v0 = C[mt*4+nt][half*2+0] + bias[n];
                float v1 = C[mt*4+nt][half*2+1] + bias[n + 1];
                *(float2*)(out + (size_t)m * DIM + n) = make_float2(v0, v1);
            }
        }
    }
}

// ===========================================================================
// Flash attention: EXACT R7 structure (measured-good). 64-row CTAs (4 warps),
// 3 CTAs/SM, 128-key tiles, single-buffer cp.async staging.
// K/V already tf32-rounded in gmem; Q rounded (rna) at staging.
// ===========================================================================
#define FPITCH 68
#define FTILE (128 * FPITCH)               // u32 per tile
#define FLASH_SMEM (2 * FTILE * 4)         // 69,632 B

__global__ __launch_bounds__(128, 3) void flash_attn_mma() {
    extern __shared__ uint32_t sbuf[];
    uint32_t* bufK = sbuf;
    uint32_t* bufV = sbuf + FTILE;
    const uint32_t skb = smem_u32(bufK);
    const uint32_t svb = smem_u32(bufV);

    const int tid  = threadIdx.x;
    const int wid  = tid >> 5;             // 0..3
    const int lane = tid & 31;
    const int qp   = lane >> 2;
    const int c    = lane & 3;

    const int bh = blockIdx.x >> 6;        // 0..15
    const int qt = blockIdx.x & 63;        // 64-row query tile

    const float* qbase = g_q + ((size_t)bh * SEQ + (size_t)qt * 64) * HEAD_DIM;
    const float* kbase = g_k + (size_t)bh * SEQ * HEAD_DIM;
    const float* vbase = g_v + (size_t)bh * SEQ * HEAD_DIM;

    // Stage Q (scaled, rna) into bufK temporarily, extract A-fragments.
#pragma unroll
    for (int i = 0; i < 8; i++) {
        int idx = tid + i * 128;           // 0..1023
        int row = idx >> 4, c4 = (idx & 15) * 4;
        float4 v = *(const float4*)(qbase + (size_t)row * HEAD_DIM + c4);
        uint4 u;
        u.x = f2tf32(v.x * ATTN_SCALE); u.y = f2tf32(v.y * ATTN_SCALE);
        u.z = f2tf32(v.z * ATTN_SCALE); u.w = f2tf32(v.w * ATTN_SCALE);
        *(uint4*)(bufK + row * FPITCH + c4) = u;
    }
    __syncthreads();

    uint32_t qa[32];
#pragma unroll
    for (int ks = 0; ks < 8; ks++) {
        const uint32_t* qlo = bufK + (wid * 16 + qp) * FPITCH + ks * 8 + c;
        const uint32_t* qhi = qlo + 8 * FPITCH;
        qa[ks*4+0] = qlo[0];
        qa[ks*4+1] = qhi[0];
        qa[ks*4+2] = qlo[4];
        qa[ks*4+3] = qhi[4];
    }
    __syncthreads();

    float oc[8][4];
#pragma unroll
    for (int t = 0; t < 8; t++)
#pragma unroll
        for (int r = 0; r < 4; r++) oc[t][r] = 0.f;
    float m_lo = -1e30f, m_hi = -1e30f;
    float l_lo = 0.f,    l_hi = 0.f;

    for (int kt = 0; kt < SEQ / 128; kt++) {
        // ---- Stage K, V via cp.async (raw, pre-rounded fp32) ----
#pragma unroll
        for (int i = 0; i < 16; i++) {
            int idx = tid + i * 128;       // 0..2047 chunks of 16B
            int row = idx >> 4, c4 = (idx & 15) * 4;
            uint32_t soff = (uint32_t)(row * FPITCH + c4) * 4u;
            const float* gk = kbase + ((size_t)kt * 128 + row) * HEAD_DIM + c4;
            const float* gv = vbase + ((size_t)kt * 128 + row) * HEAD_DIM + c4;
            CP_ASYNC16(skb + soff, gk);
            CP_ASYNC16(svb + soff, gv);
        }
        CP_COMMIT();
        CP_WAIT0();
        __syncthreads();

        // ---- S = Q @ K^T ----
        float sc[16][4];
#pragma unroll
        for (int t = 0; t < 16; t++)
#pragma unroll
            for (int r = 0; r < 4; r++) sc[t][r] = 0.f;

#pragma unroll
        for (int nt = 0; nt < 16; nt++) {
            const uint32_t* kr = bufK + (nt * 8 + qp) * FPITCH + c;
#pragma unroll
            for (int ks = 0; ks < 8; ks++) {
                uint32_t b0 = kr[ks * 8];
                uint32_t b1 = kr[ks * 8 + 4];
                mma_tf32(sc[nt], qa + ks * 4, b0, b1);
            }
        }

        // ---- Online softmax (quad-level reductions) ----
        float mx_lo = -1e30f, mx_hi = -1e30f;
#pragma unroll
        for (int t = 0; t < 16; t++) {
            mx_lo = fmaxf(mx_lo, fmaxf(sc[t][0], sc[t][1]));
            mx_hi = fmaxf(mx_hi, fmaxf(sc[t][2], sc[t][3]));
        }
        mx_lo = fmaxf(mx_lo, __shfl_xor_sync(0xffffffffu, mx_lo, 1));
        mx_lo = fmaxf(mx_lo, __shfl_xor_sync(0xffffffffu, mx_lo, 2));
        mx_hi = fmaxf(mx_hi, __shfl_xor_sync(0xffffffffu, mx_hi, 1));
        mx_hi = fmaxf(mx_hi, __shfl_xor_sync(0xffffffffu, mx_hi, 2));

        float mn_lo = fmaxf(m_lo, mx_lo);
        float mn_hi = fmaxf(m_hi, mx_hi);
        float al_lo = __expf(m_lo - mn_lo);
        float al_hi = __expf(m_hi - mn_hi);
        m_lo = mn_lo; m_hi = mn_hi;

        float s_lo = 0.f, s_hi = 0.f;
#pragma unroll
        for (int t = 0; t < 16; t++) {
            sc[t][0] = __expf(sc[t][0] - mn_lo);
            sc[t][1] = __expf(sc[t][1] - mn_lo);
            sc[t][2] = __expf(sc[t][2] - mn_hi);
            sc[t][3] = __expf(sc[t][3] - mn_hi);
            s_lo += sc[t][0] + sc[t][1];
            s_hi += sc[t][2] + sc[t][3];
        }
        l_lo = al_lo * l_lo + s_lo;
        l_hi = al_hi * l_hi + s_hi;

#pragma unroll
        for (int t = 0; t < 8; t++) {
            oc[t][0] *= al_lo; oc[t][1] *= al_lo;
            oc[t][2] *= al_hi; oc[t][3] *= al_hi;
        }

        // ---- O += P @ V ----
#pragma unroll
        for (int ks = 0; ks < 16; ks++) {
            int s0 = c >> 1;
            int s1 = 2 + (c >> 1);
            float t0 = __shfl_sync(0xffffffffu, sc[ks][0], s0, 4);
            float t1 = __shfl_sync(0xffffffffu, sc[ks][1], s0, 4);
            float t2 = __shfl_sync(0xffffffffu, sc[ks][2], s0, 4);
            float t3 = __shfl_sync(0xffffffffu, sc[ks][3], s0, 4);
            float u0 = __shfl_sync(0xffffffffu, sc[ks][0], s1, 4);
            float u1 = __shfl_sync(0xffffffffu, sc[ks][1], s1, 4);
            float u2 = __shfl_sync(0xffffffffu, sc[ks][2], s1, 4);
            float u3 = __shfl_sync(0xffffffffu, sc[ks][3], s1, 4);
            uint32_t a[4];
            a[0] = __float_as_uint((c & 1) ? t1 : t0);
            a[1] = __float_as_uint((c & 1) ? t3 : t2);
            a[2] = __float_as_uint((c & 1) ? u1 : u0);
            a[3] = __float_as_uint((c & 1) ? u3 : u2);

            const uint32_t* vr = bufV + (ks * 8 + c) * FPITCH + qp;
#pragma unroll
            for (int nt = 0; nt < 8; nt++) {
                uint32_t b0 = vr[nt * 8];
                uint32_t b1 = vr[4 * FPITCH + nt * 8];
                mma_tf32(oc[nt], a, b0, b1);
            }
        }
        __syncthreads();
    }

    // ---- Final: reduce l across quad, normalize, write ----
    l_lo += __shfl_xor_sync(0xffffffffu, l_lo, 1);
    l_lo += __shfl_xor_sync(0xffffffffu, l_lo, 2);
    l_hi += __shfl_xor_sync(0xffffffffu, l_hi, 1);
    l_hi += __shfl_xor_sync(0xffffffffu, l_hi, 2);
    const float inv_lo = 1.f / l_lo;
    const float inv_hi = 1.f / l_hi;

    const int b = bh >> 3, h = bh & 7;
    const int n_lo = qt * 64 + wid * 16 + qp;
    const int n_hi = n_lo + 8;
    float* olo = g_attn + (((size_t)b * SEQ + n_lo) * HEADS + h) * HEAD_DIM;
    float* ohi = g_attn + (((size_t)b * SEQ + n_hi) * HEADS + h) * HEAD_DIM;
#pragma unroll
    for (int t = 0; t < 8; t++) {
        int d = t * 8 + c * 2;
        *(float2*)(olo + d) = make_float2(oc[t][0] * inv_lo, oc[t][1] * inv_lo);
        *(float2*)(ohi + d) = make_float2(oc[t][2] * inv_hi, oc[t][3] * inv_hi);
    }
}

// ---------------------------------------------------------------------------

extern "C" void kernel_launch(void* const* d_in, const int* in_sizes, int n_in,
                              void* d_out, int out_size) {
    const float* x      = (const float*)d_in[0];
    const float* qkv_w  = (const float*)d_in[1];
    const float* qkv_b  = (const float*)d_in[2];
    const float* proj_w = (const float*)d_in[3];
    const float* proj_b = (const float*)d_in[4];
    float* out = (float*)d_out;

    cudaFuncSetAttribute(qkv_gemm_tc,
                         cudaFuncAttributeMaxDynamicSharedMemorySize, GEMM_SMEM);
    cudaFuncSetAttribute(proj_gemm_tc,
                         cudaFuncAttributeMaxDynamicSharedMemorySize, GEMM_SMEM);
    cudaFuncSetAttribute(flash_attn_mma,
                         cudaFuncAttributeMaxDynamicSharedMemorySize, FLASH_SMEM);

    qkv_gemm_tc<<<dim3(12, 64), 256, GEMM_SMEM>>>(x, qkv_w, qkv_b);
    flash_attn_mma<<<16 * (SEQ / 64), 128, FLASH_SMEM>>>();
    proj_gemm_tc<<<dim3(4, 64), 256, GEMM_SMEM>>>(proj_w, proj_b, out);
}

// round 11
// speedup vs baseline: 1.8817x; 1.1310x over previous
#include <cuda_runtime.h>
#include <cstdint>

#define DIM 512
#define HEADS 8
#define HEAD_DIM 64
#define BATCH 2
#define SEQ 4096
#define M_TOT (BATCH*SEQ)           // 8192
#define ATTN_SCALE 0.125f           // 64^-0.5
#define QSCALE (0.125f * 1.44269504088896340736f)   // SCALE * log2(e)

// Scratch (allocation-free: device globals)
__device__ float g_q[BATCH*HEADS*SEQ*HEAD_DIM];
__device__ float g_k[BATCH*HEADS*SEQ*HEAD_DIM];
__device__ float g_v[BATCH*HEADS*SEQ*HEAD_DIM];
__device__ float g_attn[M_TOT*DIM];

// ---------------------------------------------------------------------------
// mma.sync m16n8k8 tf32 (baseline PTX) + helpers
// ---------------------------------------------------------------------------
__device__ __forceinline__ void mma_tf32(float* d, const uint32_t* a,
                                         uint32_t b0, uint32_t b1) {
    asm volatile(
        "mma.sync.aligned.m16n8k8.row.col.f32.tf32.tf32.f32 "
        "{%0,%1,%2,%3}, {%4,%5,%6,%7}, {%8,%9}, {%0,%1,%2,%3};"
        : "+f"(d[0]), "+f"(d[1]), "+f"(d[2]), "+f"(d[3])
        : "r"(a[0]), "r"(a[1]), "r"(a[2]), "r"(a[3]), "r"(b0), "r"(b1));
}

__device__ __forceinline__ uint32_t f2tf32(float x) {
    uint32_t r;
    asm("cvt.rna.tf32.f32 %0, %1;" : "=r"(r) : "f"(x));
    return r;
}

__device__ __forceinline__ uint32_t smem_u32(const void* p) {
    uint32_t a;
    asm("{ .reg .u64 t; cvta.to.shared.u64 t, %1; cvt.u32.u64 %0, t; }"
        : "=r"(a) : "l"(p));
    return a;
}

#define CP_ASYNC16(dst, src) \
    asm volatile("cp.async.cg.shared.global [%0], [%1], 16;" \
                 :: "r"(dst), "l"(src) : "memory")
#define CP_COMMIT() asm volatile("cp.async.commit_group;" ::: "memory")
#define CP_WAIT0()  asm volatile("cp.async.wait_group 0;" ::: "memory")

// ===========================================================================
// Split-precision tf32 tensor GEMM (UNCHANGED from 937us best).
// ===========================================================================
#define GP 20
#define GST (128 * GP)
#define GEMM_SMEM (8 * GST * 4)        // 81,920 B

#define SPLIT_STORE(BH, BL, off, v) do {                                     \
    uint4 _h, _l;                                                            \
    _h.x = f2tf32((v).x); _l.x = f2tf32((v).x - __uint_as_float(_h.x));      \
    _h.y = f2tf32((v).y); _l.y = f2tf32((v).y - __uint_as_float(_h.y));      \
    _h.z = f2tf32((v).z); _l.z = f2tf32((v).z - __uint_as_float(_h.z));      \
    _h.w = f2tf32((v).w); _l.w = f2tf32((v).w - __uint_as_float(_h.w));      \
    *(uint4*)((BH) + (off)) = _h;                                            \
    *(uint4*)((BL) + (off)) = _l;                                            \
} while (0)

#define LOAD_AFRAG(dst, BUF, off)                                            \
    _Pragma("unroll")                                                        \
    for (int mt = 0; mt < 4; mt++) {                                         \
        int _o = (off) + mt * 16 * GP;                                       \
        (dst)[mt*4+0] = (BUF)[_o];                                           \
        (dst)[mt*4+1] = (BUF)[_o + 8 * GP];                                  \
        (dst)[mt*4+2] = (BUF)[_o + 4];                                       \
        (dst)[mt*4+3] = (BUF)[_o + 8 * GP + 4];                              \
    }
#define LOAD_BFRAG(dst, BUF, off)                                            \
    _Pragma("unroll")                                                        \
    for (int nt = 0; nt < 4; nt++) {                                         \
        int _o = (off) + nt * 8 * GP;                                        \
        (dst)[nt*2+0] = (BUF)[_o];                                           \
        (dst)[nt*2+1] = (BUF)[_o + 4];                                       \
    }
#define MMA_PASS(AF, BF)                                                     \
    _Pragma("unroll")                                                        \
    for (int mt = 0; mt < 4; mt++)                                           \
        _Pragma("unroll")                                                    \
        for (int nt = 0; nt < 4; nt++)                                       \
            mma_tf32(C[mt*4+nt], (AF) + mt*4, (BF)[nt*2], (BF)[nt*2+1]);

#define GEMM_BODY(Aptr, Wptr)                                                \
    extern __shared__ uint32_t gsm[];                                        \
    uint32_t* Ah = gsm;                                                      \
    uint32_t* Al = gsm + 2 * GST;                                            \
    uint32_t* Wh = gsm + 4 * GST;                                            \
    uint32_t* Wl = gsm + 6 * GST;                                            \
    const int tid  = threadIdx.x;                                            \
    const int m0   = blockIdx.y * 128;                                       \
    const int n0   = blockIdx.x * 128;                                       \
    const int wid  = tid >> 5, lane = tid & 31;                              \
    const int qp   = lane >> 2, c = lane & 3;                                \
    const int wm   = (wid >> 2) * 64;                                        \
    const int wn   = (wid & 3) * 32;                                         \
    float C[16][4];                                                          \
    _Pragma("unroll")                                                        \
    for (int t = 0; t < 16; t++)                                             \
        { C[t][0] = 0.f; C[t][1] = 0.f; C[t][2] = 0.f; C[t][3] = 0.f; }      \
    const int srow0 = tid >> 2, sc4 = (tid & 3) * 4;                         \
    const int srow1 = srow0 + 64;                                            \
    {                                                                        \
        float4 a0 = *(const float4*)(Aptr + (size_t)(m0 + srow0) * DIM + sc4); \
        float4 a1 = *(const float4*)(Aptr + (size_t)(m0 + srow1) * DIM + sc4); \
        float4 w0 = *(const float4*)(Wptr + (size_t)(n0 + srow0) * DIM + sc4); \
        float4 w1 = *(const float4*)(Wptr + (size_t)(n0 + srow1) * DIM + sc4); \
        SPLIT_STORE(Ah, Al, srow0 * GP + sc4, a0);                           \
        SPLIT_STORE(Ah, Al, srow1 * GP + sc4, a1);                           \
        SPLIT_STORE(Wh, Wl, srow0 * GP + sc4, w0);                           \
        SPLIT_STORE(Wh, Wl, srow1 * GP + sc4, w1);                           \
    }                                                                        \
    __syncthreads();                                                         \
    for (int s = 0; s < DIM / 16; s++) {                                     \
        const int cur = (s & 1) * GST;                                       \
        float4 pa0, pa1, pw0, pw1;                                           \
        if (s < DIM / 16 - 1) {                                              \
            int nk = (s + 1) * 16;                                           \
            pa0 = *(const float4*)(Aptr + (size_t)(m0 + srow0) * DIM + nk + sc4); \
            pa1 = *(const float4*)(Aptr + (size_t)(m0 + srow1) * DIM + nk + sc4); \
            pw0 = *(const float4*)(Wptr + (size_t)(n0 + srow0) * DIM + nk + sc4); \
            pw1 = *(const float4*)(Wptr + (size_t)(n0 + srow1) * DIM + nk + sc4); \
        }                                                                    \
        _Pragma("unroll")                                                    \
        for (int kk = 0; kk < 2; kk++) {                                     \
            const int aoff = cur + (wm + qp) * GP + kk * 8 + c;              \
            const int boff = cur + (wn + qp) * GP + kk * 8 + c;              \
            uint32_t af[16], bf[8];                                          \
            LOAD_AFRAG(af, Ah, aoff)                                         \
            LOAD_BFRAG(bf, Wh, boff)                                         \
            MMA_PASS(af, bf)                                                 \
            {                                                                \
                uint32_t bl[8];                                              \
                LOAD_BFRAG(bl, Wl, boff)                                     \
                MMA_PASS(af, bl)                                             \
            }                                                                \
            LOAD_AFRAG(af, Al, aoff)                                         \
            MMA_PASS(af, bf)                                                 \
        }                                                                    \
        if (s < DIM / 16 - 1) {                                              \
            const int nb = ((s + 1) & 1) * GST;                              \
            SPLIT_STORE(Ah + nb, Al + nb, srow0 * GP + sc4, pa0);            \
            SPLIT_STORE(Ah + nb, Al + nb, srow1 * GP + sc4, pa1);            \
            SPLIT_STORE(Wh + nb, Wl + nb, srow0 * GP + sc4, pw0);            \
            SPLIT_STORE(Wh + nb, Wl + nb, srow1 * GP + sc4, pw1);            \
        }                                                                    \
        __syncthreads();                                                     \
    }

__global__ __launch_bounds__(256, 2) void qkv_gemm_tc(const float* __restrict__ A,
                                                      const float* __restrict__ W,
                                                      const float* __restrict__ bias) {
    GEMM_BODY(A, W)
#pragma unroll
    for (int mt = 0; mt < 4; mt++) {
#pragma unroll
        for (int nt = 0; nt < 4; nt++) {
#pragma unroll
            for (int half = 0; half < 2; half++) {
                int m  = m0 + wm + mt * 16 + qp + half * 8;
                int b  = m >> 12;
                int nn = m & 4095;
                int n  = n0 + wn + nt * 8 + c * 2;
                float v0 = C[mt*4+nt][half*2+0] + bias[n];
                float v1 = C[mt*4+nt][half*2+1] + bias[n + 1];
                int which = n >> 9;
                int cc = n & 511;
                int h  = cc >> 6;
                int d  = cc & 63;
                int bhh = b * HEADS + h;
                if (which != 0) {
                    v0 = __uint_as_float(f2tf32(v0));
                    v1 = __uint_as_float(f2tf32(v1));
                }
                float* dst = (which == 0) ? g_q : ((which == 1) ? g_k : g_v);
                *(float2*)(dst + ((size_t)bhh * SEQ + nn) * HEAD_DIM + d) =
                    make_float2(v0, v1);
            }
        }
    }
}

__global__ __launch_bounds__(256, 2) void proj_gemm_tc(const float* __restrict__ W,
                                                       const float* __restrict__ bias,
                                                       float* __restrict__ out) {
    const float* Ain = g_attn;
    GEMM_BODY(Ain, W)
#pragma unroll
    for (int mt = 0; mt < 4; mt++) {
#pragma unroll
        for (int nt = 0; nt < 4; nt++) {
#pragma unroll
            for (int half = 0; half < 2; half++) {
                int m = m0 + wm + mt * 16 + qp + half * 8;
                int n = n0 + wn + nt * 8 + c * 2;
                float v0 = C[mt*4+nt][half*2+0] + bias[n];
                float v1 = C[mt*4+nt][half*2+1] + bias[n + 1];
                *(float2*)(out + (size_t)m * DIM + n) = make_float2(v0, v1);
            }
        }
    }
}

// ===========================================================================
// Flash attention v2: 128-query CTAs, 4 warps x 32 rows (2 m-tiles/warp),
// 64-key tiles. B-fragments amortized over 2 m-tiles. K pitch 68 (S-pass
// conflict-free), V pitch 72 (PV-pass conflict-free: 72 == 8 mod 32).
// exp2-domain softmax (Q pre-scaled by SCALE*log2e).
// ===========================================================================
#define KP 68
#define VP 72
#define KTILE_U32 (64 * KP)                 // 4352
#define VTILE_U32 (64 * VP)                 // 4608
#define FLASH_SMEM ((KTILE_U32 + VTILE_U32) * 4)   // 35,840 B
#define NKT (SEQ / 64)

__global__ __launch_bounds__(128, 2) void flash_attn_mma() {
    extern __shared__ uint32_t sbuf[];
    uint32_t* bufK = sbuf;                  // 64 x KP
    uint32_t* bufV = sbuf + KTILE_U32;      // 64 x VP
    const uint32_t skb = smem_u32(bufK);
    const uint32_t svb = smem_u32(bufV);

    const int tid  = threadIdx.x;
    const int wid  = tid >> 5;              // 0..3, owns rows wid*32..+31
    const int lane = tid & 31;
    const int qp   = lane >> 2;
    const int c    = lane & 3;

    const int bh = blockIdx.x >> 5;         // 0..15
    const int qt = blockIdx.x & 31;         // 128-row query tile

    const float* qbase = g_q + ((size_t)bh * SEQ + (size_t)qt * 128) * HEAD_DIM;
    const float* kbase = g_k + (size_t)bh * SEQ * HEAD_DIM;
    const float* vbase = g_v + (size_t)bh * SEQ * HEAD_DIM;

    // ---- Stage Q (scaled by SCALE*log2e, rna): rows 0..63 -> bufK (pitch KP),
    //      rows 64..127 -> bufV (pitch KP within V space; fits since VP>KP) ----
#pragma unroll
    for (int i = 0; i < 16; i++) {
        int idx = tid + i * 128;            // 0..2047
        int row = idx >> 4, c4 = (idx & 15) * 4;
        float4 v = *(const float4*)(qbase + (size_t)row * HEAD_DIM + c4);
        uint4 u;
        u.x = f2tf32(v.x * QSCALE); u.y = f2tf32(v.y * QSCALE);
        u.z = f2tf32(v.z * QSCALE); u.w = f2tf32(v.w * QSCALE);
        uint32_t* dst = (row < 64) ? (bufK + row * KP) : (bufV + (row - 64) * KP);
        *(uint4*)(dst + c4) = u;
    }
    __syncthreads();

    // A-fragments for this warp's 2 m-tiles (rows wid*32 + mt*16 + ...)
    uint32_t qa[2][32];
    {
        const uint32_t* base = (wid < 2) ? bufK : bufV;
        int rbase = (wid & 1) * 32;
#pragma unroll
        for (int mt = 0; mt < 2; mt++) {
#pragma unroll
            for (int ks = 0; ks < 8; ks++) {
                const uint32_t* qlo = base + (rbase + mt * 16 + qp) * KP + ks * 8 + c;
                const uint32_t* qhi = qlo + 8 * KP;
                qa[mt][ks*4+0] = qlo[0];
                qa[mt][ks*4+1] = qhi[0];
                qa[mt][ks*4+2] = qlo[4];
                qa[mt][ks*4+3] = qhi[4];
            }
        }
    }
    __syncthreads();

    float oc[2][8][4];
#pragma unroll
    for (int mt = 0; mt < 2; mt++)
#pragma unroll
        for (int t = 0; t < 8; t++)
#pragma unroll
            for (int r = 0; r < 4; r++) oc[mt][t][r] = 0.f;
    float mrun[4] = {-1e30f, -1e30f, -1e30f, -1e30f};  // [mt*2 + hi]
    float lrun[4] = {0.f, 0.f, 0.f, 0.f};

    for (int kt = 0; kt < NKT; kt++) {
        // ---- Stage K (pitch 68), V (pitch 72) via cp.async ----
#pragma unroll
        for (int i = 0; i < 8; i++) {
            int idx = tid + i * 128;        // 0..1023
            int row = idx >> 4, c4 = (idx & 15) * 4;
            const float* gk = kbase + ((size_t)kt * 64 + row) * HEAD_DIM + c4;
            const float* gv = vbase + ((size_t)kt * 64 + row) * HEAD_DIM + c4;
            CP_ASYNC16(skb + (uint32_t)(row * KP + c4) * 4u, gk);
            CP_ASYNC16(svb + (uint32_t)(row * VP + c4) * 4u, gv);
        }
        CP_COMMIT();
        CP_WAIT0();
        __syncthreads();

        // ---- S = Q @ K^T : 8 n-tiles x 8 ks, B-frag shared by both m-tiles ----
        float sc[2][8][4];
#pragma unroll
        for (int mt = 0; mt < 2; mt++)
#pragma unroll
            for (int t = 0; t < 8; t++)
#pragma unroll
                for (int r = 0; r < 4; r++) sc[mt][t][r] = 0.f;

#pragma unroll
        for (int nt = 0; nt < 8; nt++) {
            const uint32_t* kr = bufK + (nt * 8 + qp) * KP + c;
#pragma unroll
            for (int ks = 0; ks < 8; ks++) {
                uint32_t b0 = kr[ks * 8];
                uint32_t b1 = kr[ks * 8 + 4];
                mma_tf32(sc[0][nt], qa[0] + ks * 4, b0, b1);
                mma_tf32(sc[1][nt], qa[1] + ks * 4, b0, b1);
            }
        }

        // ---- Online softmax (exp2 domain), per m-tile ----
        float alpha[4];
#pragma unroll
        for (int mt = 0; mt < 2; mt++) {
            float mx_lo = -1e30f, mx_hi = -1e30f;
#pragma unroll
            for (int t = 0; t < 8; t++) {
                mx_lo = fmaxf(mx_lo, fmaxf(sc[mt][t][0], sc[mt][t][1]));
                mx_hi = fmaxf(mx_hi, fmaxf(sc[mt][t][2], sc[mt][t][3]));
            }
            mx_lo = fmaxf(mx_lo, __shfl_xor_sync(0xffffffffu, mx_lo, 1));
            mx_lo = fmaxf(mx_lo, __shfl_xor_sync(0xffffffffu, mx_lo, 2));
            mx_hi = fmaxf(mx_hi, __shfl_xor_sync(0xffffffffu, mx_hi, 1));
            mx_hi = fmaxf(mx_hi, __shfl_xor_sync(0xffffffffu, mx_hi, 2));

            float mn_lo = fmaxf(mrun[mt*2+0], mx_lo);
            float mn_hi = fmaxf(mrun[mt*2+1], mx_hi);
            alpha[mt*2+0] = exp2f(mrun[mt*2+0] - mn_lo);
            alpha[mt*2+1] = exp2f(mrun[mt*2+1] - mn_hi);
            mrun[mt*2+0] = mn_lo; mrun[mt*2+1] = mn_hi;

            float s_lo = 0.f, s_hi = 0.f;
#pragma unroll
            for (int t = 0; t < 8; t++) {
                sc[mt][t][0] = exp2f(sc[mt][t][0] - mn_lo);
                sc[mt][t][1] = exp2f(sc[mt][t][1] - mn_lo);
                sc[mt][t][2] = exp2f(sc[mt][t][2] - mn_hi);
                sc[mt][t][3] = exp2f(sc[mt][t][3] - mn_hi);
                s_lo += sc[mt][t][0] + sc[mt][t][1];
                s_hi += sc[mt][t][2] + sc[mt][t][3];
            }
            lrun[mt*2+0] = alpha[mt*2+0] * lrun[mt*2+0] + s_lo;
            lrun[mt*2+1] = alpha[mt*2+1] * lrun[mt*2+1] + s_hi;

#pragma unroll
            for (int t = 0; t < 8; t++) {
                oc[mt][t][0] *= alpha[mt*2+0]; oc[mt][t][1] *= alpha[mt*2+0];
                oc[mt][t][2] *= alpha[mt*2+1]; oc[mt][t][3] *= alpha[mt*2+1];
            }
        }

        // ---- O += P @ V : 8 key octets; V B-frag shared by both m-tiles ----
#pragma unroll
        for (int ks = 0; ks < 8; ks++) {
            uint32_t a0[4], a1[4];
            int s0 = c >> 1;
            int s1 = 2 + (c >> 1);
#pragma unroll
            for (int mt = 0; mt < 2; mt++) {
                float t0 = __shfl_sync(0xffffffffu, sc[mt][ks][0], s0, 4);
                float t1 = __shfl_sync(0xffffffffu, sc[mt][ks][1], s0, 4);
                float t2 = __shfl_sync(0xffffffffu, sc[mt][ks][2], s0, 4);
                float t3 = __shfl_sync(0xffffffffu, sc[mt][ks][3], s0, 4);
                float u0 = __shfl_sync(0xffffffffu, sc[mt][ks][0], s1, 4);
                float u1 = __shfl_sync(0xffffffffu, sc[mt][ks][1], s1, 4);
                float u2 = __shfl_sync(0xffffffffu, sc[mt][ks][2], s1, 4);
                float u3 = __shfl_sync(0xffffffffu, sc[mt][ks][3], s1, 4);
                uint32_t* a = (mt == 0) ? a0 : a1;
                a[0] = __float_as_uint((c & 1) ? t1 : t0);
                a[1] = __float_as_uint((c & 1) ? t3 : t2);
                a[2] = __float_as_uint((c & 1) ? u1 : u0);
                a[3] = __float_as_uint((c & 1) ? u3 : u2);
            }

            const uint32_t* vr = bufV + (ks * 8 + c) * VP + qp;
#pragma unroll
            for (int nt = 0; nt < 8; nt++) {
                uint32_t b0 = vr[nt * 8];
                uint32_t b1 = vr[4 * VP + nt * 8];
                mma_tf32(oc[0][nt], a0, b0, b1);
                mma_tf32(oc[1][nt], a1, b0, b1);
            }
        }
        __syncthreads();
    }

    // ---- Final: reduce l across quad, normalize, write ----
#pragma unroll
    for (int j = 0; j < 4; j++) {
        lrun[j] += __shfl_xor_sync(0xffffffffu, lrun[j], 1);
        lrun[j] += __shfl_xor_sync(0xffffffffu, lrun[j], 2);
        lrun[j] = 1.f / lrun[j];
    }

    const int b = bh >> 3, h = bh & 7;
#pragma unroll
    for (int mt = 0; mt < 2; mt++) {
        const int n_lo = qt * 128 + wid * 32 + mt * 16 + qp;
        const int n_hi = n_lo + 8;
        float* olo = g_attn + (((size_t)b * SEQ + n_lo) * HEADS + h) * HEAD_DIM;
        float* ohi = g_attn + (((size_t)b * SEQ + n_hi) * HEADS + h) * HEAD_DIM;
        const float inv_lo = lrun[mt*2+0];
        const float inv_hi = lrun[mt*2+1];
#pragma unroll
        for (int t = 0; t < 8; t++) {
            int d = t * 8 + c * 2;
            *(float2*)(olo + d) = make_float2(oc[mt][t][0] * inv_lo,
                                              oc[mt][t][1] * inv_lo);
            *(float2*)(ohi + d) = make_float2(oc[mt][t][2] * inv_hi,
                                              oc[mt][t][3] * inv_hi);
        }
    }
}

// ---------------------------------------------------------------------------

extern "C" void kernel_launch(void* const* d_in, const int* in_sizes, int n_in,
                              void* d_out, int out_size) {
    const float* x      = (const float*)d_in[0];
    const float* qkv_w  = (const float*)d_in[1];
    const float* qkv_b  = (const float*)d_in[2];
    const float* proj_w = (const float*)d_in[3];
    const float* proj_b = (const float*)d_in[4];
    float* out = (float*)d_out;

    cudaFuncSetAttribute(qkv_gemm_tc,
                         cudaFuncAttributeMaxDynamicSharedMemorySize, GEMM_SMEM);
    cudaFuncSetAttribute(proj_gemm_tc,
                         cudaFuncAttributeMaxDynamicSharedMemorySize, GEMM_SMEM);
    cudaFuncSetAttribute(flash_attn_mma,
                         cudaFuncAttributeMaxDynamicSharedMemorySize, FLASH_SMEM);

    qkv_gemm_tc<<<dim3(12, 64), 256, GEMM_SMEM>>>(x, qkv_w, qkv_b);
    flash_attn_mma<<<16 * (SEQ / 128), 128, FLASH_SMEM>>>();
    proj_gemm_tc<<<dim3(4, 64), 256, GEMM_SMEM>>>(proj_w, proj_b, out);
}

// round 16
// speedup vs baseline: 2.7451x; 1.4588x over previous
#include <cuda_runtime.h>
#include <cuda_fp16.h>
#include <cstdint>

#define DIM 512
#define HEADS 8
#define HEAD_DIM 64
#define BATCH 2
#define SEQ 4096
#define M_TOT (BATCH*SEQ)           // 8192
#define QSCALE (0.125f * 1.44269504088896340736f)   // SCALE * log2(e)

// Scratch (allocation-free: device globals). q/k/v packed half2 (uint32 words).
__device__ uint32_t g_qh[BATCH*HEADS*SEQ*HEAD_DIM/2];
__device__ uint32_t g_kh[BATCH*HEADS*SEQ*HEAD_DIM/2];
__device__ uint32_t g_vh[BATCH*HEADS*SEQ*HEAD_DIM/2];
__device__ float    g_attn[M_TOT*DIM];

// ---------------------------------------------------------------------------
// PTX helpers (all baseline, no sm_103a-only features)
// ---------------------------------------------------------------------------
__device__ __forceinline__ void mma_tf32(float* d, const uint32_t* a,
                                         uint32_t b0, uint32_t b1) {
    asm volatile(
        "mma.sync.aligned.m16n8k8.row.col.f32.tf32.tf32.f32 "
        "{%0,%1,%2,%3}, {%4,%5,%6,%7}, {%8,%9}, {%0,%1,%2,%3};"
        : "+f"(d[0]), "+f"(d[1]), "+f"(d[2]), "+f"(d[3])
        : "r"(a[0]), "r"(a[1]), "r"(a[2]), "r"(a[3]), "r"(b0), "r"(b1));
}

__device__ __forceinline__ void mma_f16(float* d, const uint32_t* a,
                                        uint32_t b0, uint32_t b1) {
    asm volatile(
        "mma.sync.aligned.m16n8k16.row.col.f32.f16.f16.f32 "
        "{%0,%1,%2,%3}, {%4,%5,%6,%7}, {%8,%9}, {%0,%1,%2,%3};"
        : "+f"(d[0]), "+f"(d[1]), "+f"(d[2]), "+f"(d[3])
        : "r"(a[0]), "r"(a[1]), "r"(a[2]), "r"(a[3]), "r"(b0), "r"(b1));
}

__device__ __forceinline__ void ldsm_x4(uint32_t* r, uint32_t addr) {
    asm volatile("ldmatrix.sync.aligned.m8n8.x4.shared.b16 {%0,%1,%2,%3}, [%4];"
        : "=r"(r[0]), "=r"(r[1]), "=r"(r[2]), "=r"(r[3]) : "r"(addr));
}
__device__ __forceinline__ void ldsm_x4_t(uint32_t* r, uint32_t addr) {
    asm volatile("ldmatrix.sync.aligned.m8n8.x4.trans.shared.b16 {%0,%1,%2,%3}, [%4];"
        : "=r"(r[0]), "=r"(r[1]), "=r"(r[2]), "=r"(r[3]) : "r"(addr));
}

__device__ __forceinline__ uint32_t f2tf32(float x) {
    uint32_t r;
    asm("cvt.rna.tf32.f32 %0, %1;" : "=r"(r) : "f"(x));
    return r;
}

__device__ __forceinline__ uint32_t h2pack(float lo, float hi) {
    __half2 h = __floats2half2_rn(lo, hi);
    return *reinterpret_cast<uint32_t*>(&h);
}

__device__ __forceinline__ uint32_t smem_u32(const void* p) {
    uint32_t a;
    asm("{ .reg .u64 t; cvta.to.shared.u64 t, %1; cvt.u32.u64 %0, t; }"
        : "=r"(a) : "l"(p));
    return a;
}

#define CP_ASYNC16(dst, src) \
    asm volatile("cp.async.cg.shared.global [%0], [%1], 16;" \
                 :: "r"(dst), "l"(src) : "memory")
#define CP_COMMIT() asm volatile("cp.async.commit_group;" ::: "memory")
#define CP_WAIT0()  asm volatile("cp.async.wait_group 0;" ::: "memory")

// ===========================================================================
// Split-precision tf32 tensor GEMM (unchanged from the 828us best).
// ===========================================================================
#define GP 20
#define GST (128 * GP)
#define GEMM_SMEM (8 * GST * 4)        // 81,920 B

#define SPLIT_STORE(BH, BL, off, v) do {                                     \
    uint4 _h, _l;                                                            \
    _h.x = f2tf32((v).x); _l.x = f2tf32((v).x - __uint_as_float(_h.x));      \
    _h.y = f2tf32((v).y); _l.y = f2tf32((v).y - __uint_as_float(_h.y));      \
    _h.z = f2tf32((v).z); _l.z = f2tf32((v).z - __uint_as_float(_h.z));      \
    _h.w = f2tf32((v).w); _l.w = f2tf32((v).w - __uint_as_float(_h.w));      \
    *(uint4*)((BH) + (off)) = _h;                                            \
    *(uint4*)((BL) + (off)) = _l;                                            \
} while (0)

#define LOAD_AFRAG(dst, BUF, off)                                            \
    _Pragma("unroll")                                                        \
    for (int mt = 0; mt < 4; mt++) {                                         \
        int _o = (off) + mt * 16 * GP;                                       \
        (dst)[mt*4+0] = (BUF)[_o];                                           \
        (dst)[mt*4+1] = (BUF)[_o + 8 * GP];                                  \
        (dst)[mt*4+2] = (BUF)[_o + 4];                                       \
        (dst)[mt*4+3] = (BUF)[_o + 8 * GP + 4];                              \
    }
#define LOAD_BFRAG(dst, BUF, off)                                            \
    _Pragma("unroll")                                                        \
    for (int nt = 0; nt < 4; nt++) {                                         \
        int _o = (off) + nt * 8 * GP;                                        \
        (dst)[nt*2+0] = (BUF)[_o];                                           \
        (dst)[nt*2+1] = (BUF)[_o + 4];                                       \
    }
#define MMA_PASS(AF, BF)                                                     \
    _Pragma("unroll")                                                        \
    for (int mt = 0; mt < 4; mt++)                                           \
        _Pragma("unroll")                                                    \
        for (int nt = 0; nt < 4; nt++)                                       \
            mma_tf32(C[mt*4+nt], (AF) + mt*4, (BF)[nt*2], (BF)[nt*2+1]);

#define GEMM_BODY(Aptr, Wptr)                                                \
    extern __shared__ uint32_t gsm[];                                        \
    uint32_t* Ah = gsm;                                                      \
    uint32_t* Al = gsm + 2 * GST;                                            \
    uint32_t* Wh = gsm + 4 * GST;                                            \
    uint32_t* Wl = gsm + 6 * GST;                                            \
    const int tid  = threadIdx.x;                                            \
    const int m0   = blockIdx.y * 128;                                       \
    const int n0   = blockIdx.x * 128;                                       \
    const int wid  = tid >> 5, lane = tid & 31;                              \
    const int qp   = lane >> 2, c = lane & 3;                                \
    const int wm   = (wid >> 2) * 64;                                        \
    const int wn   = (wid & 3) * 32;                                         \
    float C[16][4];                                                          \
    _Pragma("unroll")                                                        \
    for (int t = 0; t < 16; t++)                                             \
        { C[t][0] = 0.f; C[t][1] = 0.f; C[t][2] = 0.f; C[t][3] = 0.f; }      \
    const int srow0 = tid >> 2, sc4 = (tid & 3) * 4;                         \
    const int srow1 = srow0 + 64;                                            \
    {                                                                        \
        float4 a0 = *(const float4*)(Aptr + (size_t)(m0 + srow0) * DIM + sc4); \
        float4 a1 = *(const float4*)(Aptr + (size_t)(m0 + srow1) * DIM + sc4); \
        float4 w0 = *(const float4*)(Wptr + (size_t)(n0 + srow0) * DIM + sc4); \
        float4 w1 = *(const float4*)(Wptr + (size_t)(n0 + srow1) * DIM + sc4); \
        SPLIT_STORE(Ah, Al, srow0 * GP + sc4, a0);                           \
        SPLIT_STORE(Ah, Al, srow1 * GP + sc4, a1);                           \
        SPLIT_STORE(Wh, Wl, srow0 * GP + sc4, w0);                           \
        SPLIT_STORE(Wh, Wl, srow1 * GP + sc4, w1);                           \
    }                                                                        \
    __syncthreads();                                                         \
    for (int s = 0; s < DIM / 16; s++) {                                     \
        const int cur = (s & 1) * GST;                                       \
        float4 pa0, pa1, pw0, pw1;                                           \
        if (s < DIM / 16 - 1) {                                              \
            int nk = (s + 1) * 16;                                           \
            pa0 = *(const float4*)(Aptr + (size_t)(m0 + srow0) * DIM + nk + sc4); \
            pa1 = *(const float4*)(Aptr + (size_t)(m0 + srow1) * DIM + nk + sc4); \
            pw0 = *(const float4*)(Wptr + (size_t)(n0 + srow0) * DIM + nk + sc4); \
            pw1 = *(const float4*)(Wptr + (size_t)(n0 + srow1) * DIM + nk + sc4); \
        }                                                                    \
        _Pragma("unroll")                                                    \
        for (int kk = 0; kk < 2; kk++) {                                     \
            const int aoff = cur + (wm + qp) * GP + kk * 8 + c;              \
            const int boff = cur + (wn + qp) * GP + kk * 8 + c;              \
            uint32_t af[16], bf[8];                                          \
            LOAD_AFRAG(af, Ah, aoff)                                         \
            LOAD_BFRAG(bf, Wh, boff)                                         \
            MMA_PASS(af, bf)                                                 \
            {                                                                \
                uint32_t bl[8];                                              \
                LOAD_BFRAG(bl, Wl, boff)                                     \
                MMA_PASS(af, bl)                                             \
            }                                                                \
            LOAD_AFRAG(af, Al, aoff)                                         \
            MMA_PASS(af, bf)                                                 \
        }                                                                    \
        if (s < DIM / 16 - 1) {                                              \
            const int nb = ((s + 1) & 1) * GST;                              \
            SPLIT_STORE(Ah + nb, Al + nb, srow0 * GP + sc4, pa0);            \
            SPLIT_STORE(Ah + nb, Al + nb, srow1 * GP + sc4, pa1);            \
            SPLIT_STORE(Wh + nb, Wl + nb, srow0 * GP + sc4, pw0);            \
            SPLIT_STORE(Wh + nb, Wl + nb, srow1 * GP + sc4, pw1);            \
        }                                                                    \
        __syncthreads();                                                     \
    }

__global__ __launch_bounds__(256, 2) void qkv_gemm_tc(const float* __restrict__ A,
                                                      const float* __restrict__ W,
                                                      const float* __restrict__ bias) {
    GEMM_BODY(A, W)
    // Epilogue: bias add, pack to half2, scatter. Q pre-scaled by SCALE*log2e.
#pragma unroll
    for (int mt = 0; mt < 4; mt++) {
#pragma unroll
        for (int nt = 0; nt < 4; nt++) {
#pragma unroll
            for (int half = 0; half < 2; half++) {
                int m  = m0 + wm + mt * 16 + qp + half * 8;
                int b  = m >> 12;
                int nn = m & 4095;
                int n  = n0 + wn + nt * 8 + c * 2;
                float v0 = C[mt*4+nt][half*2+0] + bias[n];
                float v1 = C[mt*4+nt][half*2+1] + bias[n + 1];
                int which = n >> 9;
                int cc = n & 511;
                int h  = cc >> 6;
                int d  = cc & 63;
                int bhh = b * HEADS + h;
                if (which == 0) { v0 *= QSCALE; v1 *= QSCALE; }
                uint32_t* dst = (which == 0) ? g_qh : ((which == 1) ? g_kh : g_vh);
                dst[((size_t)bhh * SEQ + nn) * (HEAD_DIM/2) + (d >> 1)] =
                    h2pack(v0, v1);
            }
        }
    }
}

__global__ __launch_bounds__(256, 2) void proj_gemm_tc(const float* __restrict__ W,
                                                       const float* __restrict__ bias,
                                                       float* __restrict__ out) {
    const float* Ain = g_attn;
    GEMM_BODY(Ain, W)
#pragma unroll
    for (int mt = 0; mt < 4; mt++) {
#pragma unroll
        for (int nt = 0; nt < 4; nt++) {
#pragma unroll
            for (int half = 0; half < 2; half++) {
                int m = m0 + wm + mt * 16 + qp + half * 8;
                int n = n0 + wn + nt * 8 + c * 2;
                float v0 = C[mt*4+nt][half*2+0] + bias[n];
                float v1 = C[mt*4+nt][half*2+1] + bias[n + 1];
                *(float2*)(out + (size_t)m * DIM + n) = make_float2(v0, v1);
            }
        }
    }
}

// ===========================================================================
// Flash attention v3: fp16 m16n8k16 datapath (FA2 layout identity).
// 128-query CTAs, 4 warps x 32 rows (2 m-tiles), 64-key tiles.
// K/V fp16 in smem, row pitch 144B (ldmatrix conflict-free).
// K via ldmatrix (non-trans = S B-frag), V via ldmatrix.trans (= PV B-frag).
// S C-frag -> PV A-frag via cvt.rn.f16x2 only (no shuffles).
// ===========================================================================
#define KPW 36                              // words (4B) per 64-dim fp16 row
#define TILE_W (64 * KPW)                   // 2304 words = 9216 B per tile
#define FLASH_SMEM (2 * TILE_W * 4)         // 18,432 B
#define NKT (SEQ / 64)

__global__ __launch_bounds__(128, 2) void flash_attn_mma() {
    extern __shared__ uint32_t sbuf[];
    uint32_t* bufK = sbuf;
    uint32_t* bufV = sbuf + TILE_W;
    const uint32_t skb = smem_u32(bufK);
    const uint32_t svb = smem_u32(bufV);

    const int tid  = threadIdx.x;
    const int wid  = tid >> 5;
    const int lane = tid & 31;
    const int qp   = lane >> 2;
    const int c    = lane & 3;

    const int bh = blockIdx.x >> 5;
    const int qt = blockIdx.x & 31;

    const uint32_t* qw = g_qh + ((size_t)bh * SEQ) * (HEAD_DIM/2);
    const uint32_t* kw = g_kh + ((size_t)bh * SEQ) * (HEAD_DIM/2);
    const uint32_t* vw = g_vh + ((size_t)bh * SEQ) * (HEAD_DIM/2);

    // ---- Q A-fragments straight from gmem (pre-scaled fp16 half2 words) ----
    uint32_t qa[2][16];
#pragma unroll
    for (int mt = 0; mt < 2; mt++) {
        int r0 = qt * 128 + wid * 32 + mt * 16 + qp;
        int r1 = r0 + 8;
#pragma unroll
        for (int ks = 0; ks < 4; ks++) {
            qa[mt][ks*4+0] = qw[(size_t)r0 * 32 + ks * 8 + c];
            qa[mt][ks*4+1] = qw[(size_t)r1 * 32 + ks * 8 + c];
            qa[mt][ks*4+2] = qw[(size_t)r0 * 32 + ks * 8 + c + 4];
            qa[mt][ks*4+3] = qw[(size_t)r1 * 32 + ks * 8 + c + 4];
        }
    }

    // ldmatrix per-lane base addresses
    const int lm = lane >> 3;               // matrix index 0..3
    const int r8 = lane & 7;                // row within matrix
    // K (non-trans): matrix = {key octet: lm>>1} x {dim-halfstep: lm&1}
    const uint32_t kbase = skb + (uint32_t)(((lm >> 1) * 8 + r8) * 144 + (lm & 1) * 16);
    // V (trans): matrix = {key octet: lm&1} x {dim octet: lm>>1}
    const uint32_t vbase = svb + (uint32_t)(((lm & 1) * 8 + r8) * 144 + (lm >> 1) * 16);

    float oc[2][8][4];
#pragma unroll
    for (int mt = 0; mt < 2; mt++)
#pragma unroll
        for (int t = 0; t < 8; t++)
#pragma unroll
            for (int r = 0; r < 4; r++) oc[mt][t][r] = 0.f;
    float mrun[4] = {-1e30f, -1e30f, -1e30f, -1e30f};
    float lrun[4] = {0.f, 0.f, 0.f, 0.f};

    for (int kt = 0; kt < NKT; kt++) {
        // ---- Stage K,V (fp16, 128B rows) via cp.async ----
#pragma unroll
        for (int i = 0; i < 8; i++) {
            int idx = tid + i * 128;        // 0..1023 16B-chunks
            int tile = idx >> 9;            // 0 = K, 1 = V
            int w    = idx & 511;
            int row  = w >> 3;
            int ch   = w & 7;
            const uint32_t* src = (tile ? vw : kw)
                + ((size_t)(kt * 64 + row)) * 32 + ch * 4;
            uint32_t dst = (tile ? svb : skb) + (uint32_t)(row * 144 + ch * 16);
            CP_ASYNC16(dst, src);
        }
        CP_COMMIT();
        CP_WAIT0();
        __syncthreads();

        // ---- S = Q @ K^T : fp16 k16, ldmatrix B-frags ----
        float sc[2][8][4];
#pragma unroll
        for (int mt = 0; mt < 2; mt++)
#pragma unroll
            for (int t = 0; t < 8; t++)
#pragma unroll
                for (int r = 0; r < 4; r++) sc[mt][t][r] = 0.f;

#pragma unroll
        for (int ntp = 0; ntp < 4; ntp++) {
#pragma unroll
            for (int ks = 0; ks < 4; ks++) {
                uint32_t kb[4];
                ldsm_x4(kb, kbase + (uint32_t)(ntp * 2304 + ks * 32));
                mma_f16(sc[0][2*ntp+0], qa[0] + ks * 4, kb[0], kb[1]);
                mma_f16(sc[1][2*ntp+0], qa[1] + ks * 4, kb[0], kb[1]);
                mma_f16(sc[0][2*ntp+1], qa[0] + ks * 4, kb[2], kb[3]);
                mma_f16(sc[1][2*ntp+1], qa[1] + ks * 4, kb[2], kb[3]);
            }
        }

        // ---- Online softmax (exp2 domain) ----
        float alpha[4];
#pragma unroll
        for (int mt = 0; mt < 2; mt++) {
            float mx_lo = -1e30f, mx_hi = -1e30f;
#pragma unroll
            for (int t = 0; t < 8; t++) {
                mx_lo = fmaxf(mx_lo, fmaxf(sc[mt][t][0], sc[mt][t][1]));
                mx_hi = fmaxf(mx_hi, fmaxf(sc[mt][t][2], sc[mt][t][3]));
            }
            mx_lo = fmaxf(mx_lo, __shfl_xor_sync(0xffffffffu, mx_lo, 1));
            mx_lo = fmaxf(mx_lo, __shfl_xor_sync(0xffffffffu, mx_lo, 2));
            mx_hi = fmaxf(mx_hi, __shfl_xor_sync(0xffffffffu, mx_hi, 1));
            mx_hi = fmaxf(mx_hi, __shfl_xor_sync(0xffffffffu, mx_hi, 2));

            float mn_lo = fmaxf(mrun[mt*2+0], mx_lo);
            float mn_hi = fmaxf(mrun[mt*2+1], mx_hi);
            alpha[mt*2+0] = exp2f(mrun[mt*2+0] - mn_lo);
            alpha[mt*2+1] = exp2f(mrun[mt*2+1] - mn_hi);
            mrun[mt*2+0] = mn_lo; mrun[mt*2+1] = mn_hi;

            float s_lo = 0.f, s_hi = 0.f;
#pragma unroll
            for (int t = 0; t < 8; t++) {
                sc[mt][t][0] = exp2f(sc[mt][t][0] - mn_lo);
                sc[mt][t][1] = exp2f(sc[mt][t][1] - mn_lo);
                sc[mt][t][2] = exp2f(sc[mt][t][2] - mn_hi);
                sc[mt][t][3] = exp2f(sc[mt][t][3] - mn_hi);
                s_lo += sc[mt][t][0] + sc[mt][t][1];
                s_hi += sc[mt][t][2] + sc[mt][t][3];
            }
            lrun[mt*2+0] = alpha[mt*2+0] * lrun[mt*2+0] + s_lo;
            lrun[mt*2+1] = alpha[mt*2+1] * lrun[mt*2+1] + s_hi;

#pragma unroll
            for (int t = 0; t < 8; t++) {
                oc[mt][t][0] *= alpha[mt*2+0]; oc[mt][t][1] *= alpha[mt*2+0];
                oc[mt][t][2] *= alpha[mt*2+1]; oc[mt][t][3] *= alpha[mt*2+1];
            }
        }

        // ---- O += P @ V : P C-frag -> A-frag via cvt; V via ldmatrix.trans ----
#pragma unroll
        for (int ks = 0; ks < 4; ks++) {
            uint32_t pa[2][4];
#pragma unroll
            for (int mt = 0; mt < 2; mt++) {
                pa[mt][0] = h2pack(sc[mt][2*ks+0][0], sc[mt][2*ks+0][1]);
                pa[mt][1] = h2pack(sc[mt][2*ks+0][2], sc[mt][2*ks+0][3]);
                pa[mt][2] = h2pack(sc[mt][2*ks+1][0], sc[mt][2*ks+1][1]);
                pa[mt][3] = h2pack(sc[mt][2*ks+1][2], sc[mt][2*ks+1][3]);
            }
#pragma unroll
            for (int ntp = 0; ntp < 4; ntp++) {
                uint32_t vb[4];
                ldsm_x4_t(vb, vbase + (uint32_t)(ks * 2304 + ntp * 32));
                mma_f16(oc[0][2*ntp+0], pa[0], vb[0], vb[1]);
                mma_f16(oc[1][2*ntp+0], pa[1], vb[0], vb[1]);
                mma_f16(oc[0][2*ntp+1], pa[0], vb[2], vb[3]);
                mma_f16(oc[1][2*ntp+1], pa[1], vb[2], vb[3]);
            }
        }
        __syncthreads();
    }

    // ---- Final: reduce l across quad, normalize, write ----
#pragma unroll
    for (int j = 0; j < 4; j++) {
        lrun[j] += __shfl_xor_sync(0xffffffffu, lrun[j], 1);
        lrun[j] += __shfl_xor_sync(0xffffffffu, lrun[j], 2);
        lrun[j] = 1.f / lrun[j];
    }

    const int b = bh >> 3, h = bh & 7;
#pragma unroll
    for (int mt = 0; mt < 2; mt++) {
        const int n_lo = qt * 128 + wid * 32 + mt * 16 + qp;
        const int n_hi = n_lo + 8;
        float* olo = g_attn + (((size_t)b * SEQ + n_lo) * HEADS + h) * HEAD_DIM;
        float* ohi = g_attn + (((size_t)b * SEQ + n_hi) * HEADS + h) * HEAD_DIM;
        const float inv_lo = lrun[mt*2+0];
        const float inv_hi = lrun[mt*2+1];
#pragma unroll
        for (int t = 0; t < 8; t++) {
            int d = t * 8 + c * 2;
            *(float2*)(olo + d) = make_float2(oc[mt][t][0] * inv_lo,
                                              oc[mt][t][1] * inv_lo);
            *(float2*)(ohi + d) = make_float2(oc[mt][t][2] * inv_hi,
                                              oc[mt][t][3] * inv_hi);
        }
    }
}

// ---------------------------------------------------------------------------

extern "C" void kernel_launch(void* const* d_in, const int* in_sizes, int n_in,
                              void* d_out, int out_size) {
    const float* x      = (const float*)d_in[0];
    const float* qkv_w  = (const float*)d_in[1];
    const float* qkv_b  = (const float*)d_in[2];
    const float* proj_w = (const float*)d_in[3];
    const float* proj_b = (const float*)d_in[4];
    float* out = (float*)d_out;

    cudaFuncSetAttribute(qkv_gemm_tc,
                         cudaFuncAttributeMaxDynamicSharedMemorySize, GEMM_SMEM);
    cudaFuncSetAttribute(proj_gemm_tc,
                         cudaFuncAttributeMaxDynamicSharedMemorySize, GEMM_SMEM);
    cudaFuncSetAttribute(flash_attn_mma,
                         cudaFuncAttributeMaxDynamicSharedMemorySize, FLASH_SMEM);

    qkv_gemm_tc<<<dim3(12, 64), 256, GEMM_SMEM>>>(x, qkv_w, qkv_b);
    flash_attn_mma<<<16 * (SEQ / 128), 128, FLASH_SMEM>>>();
    proj_gemm_tc<<<dim3(4, 64), 256, GEMM_SMEM>>>(proj_w, proj_b, out);
}

// round 17
// speedup vs baseline: 3.6764x; 1.3393x over previous
#include <cuda_runtime.h>
#include <cuda_fp16.h>
#include <cstdint>

#define DIM 512
#define HEADS 8
#define HEAD_DIM 64
#define BATCH 2
#define SEQ 4096
#define M_TOT (BATCH*SEQ)           // 8192
#define QSCALE (0.125f * 1.44269504088896340736f)   // SCALE * log2(e)

// Scratch (allocation-free: device globals). q/k/v packed half2 (uint32 words).
__device__ uint32_t g_qh[BATCH*HEADS*SEQ*HEAD_DIM/2];
__device__ uint32_t g_kh[BATCH*HEADS*SEQ*HEAD_DIM/2];
__device__ uint32_t g_vh[BATCH*HEADS*SEQ*HEAD_DIM/2];
__device__ float    g_attn[M_TOT*DIM];

// ---------------------------------------------------------------------------
// PTX helpers (all baseline, no sm_103a-only features)
// ---------------------------------------------------------------------------
__device__ __forceinline__ void mma_f16(float* d, const uint32_t* a,
                                        uint32_t b0, uint32_t b1) {
    asm volatile(
        "mma.sync.aligned.m16n8k16.row.col.f32.f16.f16.f32 "
        "{%0,%1,%2,%3}, {%4,%5,%6,%7}, {%8,%9}, {%0,%1,%2,%3};"
        : "+f"(d[0]), "+f"(d[1]), "+f"(d[2]), "+f"(d[3])
        : "r"(a[0]), "r"(a[1]), "r"(a[2]), "r"(a[3]), "r"(b0), "r"(b1));
}

__device__ __forceinline__ void ldsm_x4(uint32_t* r, uint32_t addr) {
    asm volatile("ldmatrix.sync.aligned.m8n8.x4.shared.b16 {%0,%1,%2,%3}, [%4];"
        : "=r"(r[0]), "=r"(r[1]), "=r"(r[2]), "=r"(r[3]) : "r"(addr));
}
__device__ __forceinline__ void ldsm_x4_t(uint32_t* r, uint32_t addr) {
    asm volatile("ldmatrix.sync.aligned.m8n8.x4.trans.shared.b16 {%0,%1,%2,%3}, [%4];"
        : "=r"(r[0]), "=r"(r[1]), "=r"(r[2]), "=r"(r[3]) : "r"(addr));
}

__device__ __forceinline__ uint32_t h2pack(float lo, float hi) {
    __half2 h = __floats2half2_rn(lo, hi);
    return *reinterpret_cast<uint32_t*>(&h);
}

__device__ __forceinline__ uint32_t smem_u32(const void* p) {
    uint32_t a;
    asm("{ .reg .u64 t; cvta.to.shared.u64 t, %1; cvt.u32.u64 %0, t; }"
        : "=r"(a) : "l"(p));
    return a;
}

#define CP_ASYNC16(dst, src) \
    asm volatile("cp.async.cg.shared.global [%0], [%1], 16;" \
                 :: "r"(dst), "l"(src) : "memory")
#define CP_COMMIT() asm volatile("cp.async.commit_group;" ::: "memory")
#define CP_WAIT0()  asm volatile("cp.async.wait_group 0;" ::: "memory")

// ===========================================================================
// Split-precision fp16 tensor GEMM: x = hi + lo (both fp16);
// C += Ah*Bh + Ah*Bl + Al*Bh  (~fp32 accuracy, error ~2^-22).
// CTA 128x128, BK=16 (one m16n8k16 step/stage), 256 thr, 8 warps 2m x 4n.
// Pitch 12 words/row -> fragment LDS conflict-free.
// ===========================================================================
#define GPH 12
#define GSTH (128 * GPH)               // 1536 words per stage-buffer
#define GEMM_SMEM (8 * GSTH * 4)       // 49,152 B

#define SPLIT_STORE_H(BH, BL, woff, v) do {                                  \
    __half _hx = __float2half_rn((v).x), _hy = __float2half_rn((v).y);       \
    __half _hz = __float2half_rn((v).z), _hw = __float2half_rn((v).w);       \
    __half2 _p0 = __halves2half2(_hx, _hy), _p1 = __halves2half2(_hz, _hw);  \
    (BH)[(woff)]     = *(uint32_t*)&_p0;                                     \
    (BH)[(woff) + 1] = *(uint32_t*)&_p1;                                     \
    __half2 _q0 = __floats2half2_rn((v).x - __half2float(_hx),               \
                                    (v).y - __half2float(_hy));              \
    __half2 _q1 = __floats2half2_rn((v).z - __half2float(_hz),               \
                                    (v).w - __half2float(_hw));              \
    (BL)[(woff)]     = *(uint32_t*)&_q0;                                     \
    (BL)[(woff) + 1] = *(uint32_t*)&_q1;                                     \
} while (0)

#define LOAD_AFRAG_H(dst, BUF, off)                                          \
    _Pragma("unroll")                                                        \
    for (int mt = 0; mt < 4; mt++) {                                         \
        int _o = (off) + mt * 16 * GPH;                                      \
        (dst)[mt*4+0] = (BUF)[_o];                                           \
        (dst)[mt*4+1] = (BUF)[_o + 8 * GPH];                                 \
        (dst)[mt*4+2] = (BUF)[_o + 4];                                       \
        (dst)[mt*4+3] = (BUF)[_o + 8 * GPH + 4];                             \
    }
#define LOAD_BFRAG_H(dst, BUF, off)                                          \
    _Pragma("unroll")                                                        \
    for (int nt = 0; nt < 4; nt++) {                                         \
        int _o = (off) + nt * 8 * GPH;                                       \
        (dst)[nt*2+0] = (BUF)[_o];                                           \
        (dst)[nt*2+1] = (BUF)[_o + 4];                                       \
    }
#define MMA_PASS_H(AF, BF)                                                   \
    _Pragma("unroll")                                                        \
    for (int mt = 0; mt < 4; mt++)                                           \
        _Pragma("unroll")                                                    \
        for (int nt = 0; nt < 4; nt++)                                       \
            mma_f16(C[mt*4+nt], (AF) + mt*4, (BF)[nt*2], (BF)[nt*2+1]);

#define GEMM_BODY(Aptr, Wptr)                                                \
    extern __shared__ uint32_t gsm[];                                        \
    uint32_t* Ah = gsm;                                                      \
    uint32_t* Al = gsm + 2 * GSTH;                                           \
    uint32_t* Wh = gsm + 4 * GSTH;                                           \
    uint32_t* Wl = gsm + 6 * GSTH;                                           \
    const int tid  = threadIdx.x;                                            \
    const int m0   = blockIdx.y * 128;                                       \
    const int n0   = blockIdx.x * 128;                                       \
    const int wid  = tid >> 5, lane = tid & 31;                              \
    const int qp   = lane >> 2, c = lane & 3;                                \
    const int wm   = (wid >> 2) * 64;                                        \
    const int wn   = (wid & 3) * 32;                                         \
    float C[16][4];                                                          \
    _Pragma("unroll")                                                        \
    for (int t = 0; t < 16; t++)                                             \
        { C[t][0] = 0.f; C[t][1] = 0.f; C[t][2] = 0.f; C[t][3] = 0.f; }      \
    const int srow0 = tid >> 2, sc4 = (tid & 3) * 4;                         \
    const int sw0   = (tid & 3) * 2;                                         \
    const int srow1 = srow0 + 64;                                            \
    {                                                                        \
        float4 a0 = *(const float4*)(Aptr + (size_t)(m0 + srow0) * DIM + sc4); \
        float4 a1 = *(const float4*)(Aptr + (size_t)(m0 + srow1) * DIM + sc4); \
        float4 w0 = *(const float4*)(Wptr + (size_t)(n0 + srow0) * DIM + sc4); \
        float4 w1 = *(const float4*)(Wptr + (size_t)(n0 + srow1) * DIM + sc4); \
        SPLIT_STORE_H(Ah, Al, srow0 * GPH + sw0, a0);                        \
        SPLIT_STORE_H(Ah, Al, srow1 * GPH + sw0, a1);                        \
        SPLIT_STORE_H(Wh, Wl, srow0 * GPH + sw0, w0);                        \
        SPLIT_STORE_H(Wh, Wl, srow1 * GPH + sw0, w1);                        \
    }                                                                        \
    __syncthreads();                                                         \
    for (int s = 0; s < DIM / 16; s++) {                                     \
        const int cur = (s & 1) * GSTH;                                      \
        float4 pa0, pa1, pw0, pw1;                                           \
        if (s < DIM / 16 - 1) {                                              \
            int nk = (s + 1) * 16;                                           \
            pa0 = *(const float4*)(Aptr + (size_t)(m0 + srow0) * DIM + nk + sc4); \
            pa1 = *(const float4*)(Aptr + (size_t)(m0 + srow1) * DIM + nk + sc4); \
            pw0 = *(const float4*)(Wptr + (size_t)(n0 + srow0) * DIM + nk + sc4); \
            pw1 = *(const float4*)(Wptr + (size_t)(n0 + srow1) * DIM + nk + sc4); \
        }                                                                    \
        {                                                                    \
            const int aoff = cur + (wm + qp) * GPH + c;                      \
            const int boff = cur + (wn + qp) * GPH + c;                      \
            uint32_t af[16], bf[8];                                          \
            LOAD_AFRAG_H(af, Ah, aoff)      /* ahi */                        \
            LOAD_BFRAG_H(bf, Wh, boff)      /* bhi */                        \
            MMA_PASS_H(af, bf)              /* hi*hi */                      \
            {                                                                \
                uint32_t bl[8];                                              \
                LOAD_BFRAG_H(bl, Wl, boff)  /* blo */                        \
                MMA_PASS_H(af, bl)          /* hi*lo */                      \
            }                                                                \
            LOAD_AFRAG_H(af, Al, aoff)      /* alo (overwrites ahi) */       \
            MMA_PASS_H(af, bf)              /* lo*hi */                      \
        }                                                                    \
        if (s < DIM / 16 - 1) {                                              \
            const int nb = ((s + 1) & 1) * GSTH;                             \
            SPLIT_STORE_H(Ah + nb, Al + nb, srow0 * GPH + sw0, pa0);         \
            SPLIT_STORE_H(Ah + nb, Al + nb, srow1 * GPH + sw0, pa1);         \
            SPLIT_STORE_H(Wh + nb, Wl + nb, srow0 * GPH + sw0, pw0);         \
            SPLIT_STORE_H(Wh + nb, Wl + nb, srow1 * GPH + sw0, pw1);         \
        }                                                                    \
        __syncthreads();                                                     \
    }

__global__ __launch_bounds__(256, 2) void qkv_gemm_tc(const float* __restrict__ A,
                                                      const float* __restrict__ W,
                                                      const float* __restrict__ bias) {
    GEMM_BODY(A, W)
    // Epilogue: bias add, pack to half2, scatter. Q pre-scaled by SCALE*log2e.
#pragma unroll
    for (int mt = 0; mt < 4; mt++) {
#pragma unroll
        for (int nt = 0; nt < 4; nt++) {
#pragma unroll
            for (int half = 0; half < 2; half++) {
                int m  = m0 + wm + mt * 16 + qp + half * 8;
                int b  = m >> 12;
                int nn = m & 4095;
                int n  = n0 + wn + nt * 8 + c * 2;
                float v0 = C[mt*4+nt][half*2+0] + bias[n];
                float v1 = C[mt*4+nt][half*2+1] + bias[n + 1];
                int which = n >> 9;
                int cc = n & 511;
                int h  = cc >> 6;
                int d  = cc & 63;
                int bhh = b * HEADS + h;
                if (which == 0) { v0 *= QSCALE; v1 *= QSCALE; }
                uint32_t* dst = (which == 0) ? g_qh : ((which == 1) ? g_kh : g_vh);
                dst[((size_t)bhh * SEQ + nn) * (HEAD_DIM/2) + (d >> 1)] =
                    h2pack(v0, v1);
            }
        }
    }
}

__global__ __launch_bounds__(256, 2) void proj_gemm_tc(const float* __restrict__ W,
                                                       const float* __restrict__ bias,
                                                       float* __restrict__ out) {
    const float* Ain = g_attn;
    GEMM_BODY(Ain, W)
#pragma unroll
    for (int mt = 0; mt < 4; mt++) {
#pragma unroll
        for (int nt = 0; nt < 4; nt++) {
#pragma unroll
            for (int half = 0; half < 2; half++) {
                int m = m0 + wm + mt * 16 + qp + half * 8;
                int n = n0 + wn + nt * 8 + c * 2;
                float v0 = C[mt*4+nt][half*2+0] + bias[n];
                float v1 = C[mt*4+nt][half*2+1] + bias[n + 1];
                *(float2*)(out + (size_t)m * DIM + n) = make_float2(v0, v1);
            }
        }
    }
}

// ===========================================================================
// Flash attention v3 (UNCHANGED from the 568us best): fp16 m16n8k16,
// FA2 layout identity, 128q CTAs, 4 warps x 2 m-tiles, 64-key tiles.
// ===========================================================================
#define KPW 36                              // words (4B) per 64-dim fp16 row
#define TILE_W (64 * KPW)                   // 2304 words = 9216 B per tile
#define FLASH_SMEM (2 * TILE_W * 4)         // 18,432 B
#define NKT (SEQ / 64)

__global__ __launch_bounds__(128, 2) void flash_attn_mma() {
    extern __shared__ uint32_t sbuf[];
    uint32_t* bufK = sbuf;
    uint32_t* bufV = sbuf + TILE_W;
    const uint32_t skb = smem_u32(bufK);
    const uint32_t svb = smem_u32(bufV);

    const int tid  = threadIdx.x;
    const int wid  = tid >> 5;
    const int lane = tid & 31;
    const int qp   = lane >> 2;
    const int c    = lane & 3;

    const int bh = blockIdx.x >> 5;
    const int qt = blockIdx.x & 31;

    const uint32_t* qw = g_qh + ((size_t)bh * SEQ) * (HEAD_DIM/2);
    const uint32_t* kw = g_kh + ((size_t)bh * SEQ) * (HEAD_DIM/2);
    const uint32_t* vw = g_vh + ((size_t)bh * SEQ) * (HEAD_DIM/2);

    // ---- Q A-fragments straight from gmem (pre-scaled fp16 half2 words) ----
    uint32_t qa[2][16];
#pragma unroll
    for (int mt = 0; mt < 2; mt++) {
        int r0 = qt * 128 + wid * 32 + mt * 16 + qp;
        int r1 = r0 + 8;
#pragma unroll
        for (int ks = 0; ks < 4; ks++) {
            qa[mt][ks*4+0] = qw[(size_t)r0 * 32 + ks * 8 + c];
            qa[mt][ks*4+1] = qw[(size_t)r1 * 32 + ks * 8 + c];
            qa[mt][ks*4+2] = qw[(size_t)r0 * 32 + ks * 8 + c + 4];
            qa[mt][ks*4+3] = qw[(size_t)r1 * 32 + ks * 8 + c + 4];
        }
    }

    // ldmatrix per-lane base addresses
    const int lm = lane >> 3;               // matrix index 0..3
    const int r8 = lane & 7;                // row within matrix
    const uint32_t kbase = skb + (uint32_t)(((lm >> 1) * 8 + r8) * 144 + (lm & 1) * 16);
    const uint32_t vbase = svb + (uint32_t)(((lm & 1) * 8 + r8) * 144 + (lm >> 1) * 16);

    float oc[2][8][4];
#pragma unroll
    for (int mt = 0; mt < 2; mt++)
#pragma unroll
        for (int t = 0; t < 8; t++)
#pragma unroll
            for (int r = 0; r < 4; r++) oc[mt][t][r] = 0.f;
    float mrun[4] = {-1e30f, -1e30f, -1e30f, -1e30f};
    float lrun[4] = {0.f, 0.f, 0.f, 0.f};

    for (int kt = 0; kt < NKT; kt++) {
        // ---- Stage K,V (fp16, 128B rows) via cp.async ----
#pragma unroll
        for (int i = 0; i < 8; i++) {
            int idx = tid + i * 128;        // 0..1023 16B-chunks
            int tile = idx >> 9;            // 0 = K, 1 = V
            int w    = idx & 511;
            int row  = w >> 3;
            int ch   = w & 7;
            const uint32_t* src = (tile ? vw : kw)
                + ((size_t)(kt * 64 + row)) * 32 + ch * 4;
            uint32_t dst = (tile ? svb : skb) + (uint32_t)(row * 144 + ch * 16);
            CP_ASYNC16(dst, src);
        }
        CP_COMMIT();
        CP_WAIT0();
        __syncthreads();

        // ---- S = Q @ K^T : fp16 k16, ldmatrix B-frags ----
        float sc[2][8][4];
#pragma unroll
        for (int mt = 0; mt < 2; mt++)
#pragma unroll
            for (int t = 0; t < 8; t++)
#pragma unroll
                for (int r = 0; r < 4; r++) sc[mt][t][r] = 0.f;

#pragma unroll
        for (int ntp = 0; ntp < 4; ntp++) {
#pragma unroll
            for (int ks = 0; ks < 4; ks++) {
                uint32_t kb[4];
                ldsm_x4(kb, kbase + (uint32_t)(ntp * 2304 + ks * 32));
                mma_f16(sc[0][2*ntp+0], qa[0] + ks * 4, kb[0], kb[1]);
                mma_f16(sc[1][2*ntp+0], qa[1] + ks * 4, kb[0], kb[1]);
                mma_f16(sc[0][2*ntp+1], qa[0] + ks * 4, kb[2], kb[3]);
                mma_f16(sc[1][2*ntp+1], qa[1] + ks * 4, kb[2], kb[3]);
            }
        }

        // ---- Online softmax (exp2 domain) ----
        float alpha[4];
#pragma unroll
        for (int mt = 0; mt < 2; mt++) {
            float mx_lo = -1e30f, mx_hi = -1e30f;
#pragma unroll
            for (int t = 0; t < 8; t++) {
                mx_lo = fmaxf(mx_lo, fmaxf(sc[mt][t][0], sc[mt][t][1]));
                mx_hi = fmaxf(mx_hi, fmaxf(sc[mt][t][2], sc[mt][t][3]));
            }
            mx_lo = fmaxf(mx_lo, __shfl_xor_sync(0xffffffffu, mx_lo, 1));
            mx_lo = fmaxf(mx_lo, __shfl_xor_sync(0xffffffffu, mx_lo, 2));
            mx_hi = fmaxf(mx_hi, __shfl_xor_sync(0xffffffffu, mx_hi, 1));
            mx_hi = fmaxf(mx_hi, __shfl_xor_sync(0xffffffffu, mx_hi, 2));

            float mn_lo = fmaxf(mrun[mt*2+0], mx_lo);
            float mn_hi = fmaxf(mrun[mt*2+1], mx_hi);
            alpha[mt*2+0] = exp2f(mrun[mt*2+0] - mn_lo);
            alpha[mt*2+1] = exp2f(mrun[mt*2+1] - mn_hi);
            mrun[mt*2+0] = mn_lo; mrun[mt*2+1] = mn_hi;

            float s_lo = 0.f, s_hi = 0.f;
#pragma unroll
            for (int t = 0; t < 8; t++) {
                sc[mt][t][0] = exp2f(sc[mt][t][0] - mn_lo);
                sc[mt][t][1] = exp2f(sc[mt][t][1] - mn_lo);
                sc[mt][t][2] = exp2f(sc[mt][t][2] - mn_hi);
                sc[mt][t][3] = exp2f(sc[mt][t][3] - mn_hi);
                s_lo += sc[mt][t][0] + sc[mt][t][1];
                s_hi += sc[mt][t][2] + sc[mt][t][3];
            }
            lrun[mt*2+0] = alpha[mt*2+0] * lrun[mt*2+0] + s_lo;
            lrun[mt*2+1] = alpha[mt*2+1] * lrun[mt*2+1] + s_hi;

#pragma unroll
            for (int t = 0; t < 8; t++) {
                oc[mt][t][0] *= alpha[mt*2+0]; oc[mt][t][1] *= alpha[mt*2+0];
                oc[mt][t][2] *= alpha[mt*2+1]; oc[mt][t][3] *= alpha[mt*2+1];
            }
        }

        // ---- O += P @ V : P C-frag -> A-frag via cvt; V via ldmatrix.trans ----
#pragma unroll
        for (int ks = 0; ks < 4; ks++) {
            uint32_t pa[2][4];
#pragma unroll
            for (int mt = 0; mt < 2; mt++) {
                pa[mt][0] = h2pack(sc[mt][2*ks+0][0], sc[mt][2*ks+0][1]);
                pa[mt][1] = h2pack(sc[mt][2*ks+0][2], sc[mt][2*ks+0][3]);
                pa[mt][2] = h2pack(sc[mt][2*ks+1][0], sc[mt][2*ks+1][1]);
                pa[mt][3] = h2pack(sc[mt][2*ks+1][2], sc[mt][2*ks+1][3]);
            }
#pragma unroll
            for (int ntp = 0; ntp < 4; ntp++) {
                uint32_t vb[4];
                ldsm_x4_t(vb, vbase + (uint32_t)(ks * 2304 + ntp * 32));
                mma_f16(oc[0][2*ntp+0], pa[0], vb[0], vb[1]);
                mma_f16(oc[1][2*ntp+0], pa[1], vb[0], vb[1]);
                mma_f16(oc[0][2*ntp+1], pa[0], vb[2], vb[3]);
                mma_f16(oc[1][2*ntp+1], pa[1], vb[2], vb[3]);
            }
        }
        __syncthreads();
    }

    // ---- Final: reduce l across quad, normalize, write ----
#pragma unroll
    for (int j = 0; j < 4; j++) {
        lrun[j] += __shfl_xor_sync(0xffffffffu, lrun[j], 1);
        lrun[j] += __shfl_xor_sync(0xffffffffu, lrun[j], 2);
        lrun[j] = 1.f / lrun[j];
    }

    const int b = bh >> 3, h = bh & 7;
#pragma unroll
    for (int mt = 0; mt < 2; mt++) {
        const int n_lo = qt * 128 + wid * 32 + mt * 16 + qp;
        const int n_hi = n_lo + 8;
        float* olo = g_attn + (((size_t)b * SEQ + n_lo) * HEADS + h) * HEAD_DIM;
        float* ohi = g_attn + (((size_t)b * SEQ + n_hi) * HEADS + h) * HEAD_DIM;
        const float inv_lo = lrun[mt*2+0];
        const float inv_hi = lrun[mt*2+1];
#pragma unroll
        for (int t = 0; t < 8; t++) {
            int d = t * 8 + c * 2;
            *(float2*)(olo + d) = make_float2(oc[mt][t][0] * inv_lo,
                                              oc[mt][t][1] * inv_lo);
            *(float2*)(ohi + d) = make_float2(oc[mt][t][2] * inv_hi,
                                              oc[mt][t][3] * inv_hi);
        }
    }
}

// ---------------------------------------------------------------------------

extern "C" void kernel_launch(void* const* d_in, const int* in_sizes, int n_in,
                              void* d_out, int out_size) {
    const float* x      = (const float*)d_in[0];
    const float* qkv_w  = (const float*)d_in[1];
    const float* qkv_b  = (const float*)d_in[2];
    const float* proj_w = (const float*)d_in[3];
    const float* proj_b = (const float*)d_in[4];
    float* out = (float*)d_out;

    cudaFuncSetAttribute(qkv_gemm_tc,
                         cudaFuncAttributeMaxDynamicSharedMemorySize, GEMM_SMEM);
    cudaFuncSetAttribute(proj_gemm_tc,
                         cudaFuncAttributeMaxDynamicSharedMemorySize, GEMM_SMEM);
    cudaFuncSetAttribute(flash_attn_mma,
                         cudaFuncAttributeMaxDynamicSharedMemorySize, FLASH_SMEM);

    qkv_gemm_tc<<<dim3(12, 64), 256, GEMM_SMEM>>>(x, qkv_w, qkv_b);
    flash_attn_mma<<<16 * (SEQ / 128), 128, FLASH_SMEM>>>();
    proj_gemm_tc<<<dim3(4, 64), 256, GEMM_SMEM>>>(proj_w, proj_b, out);
}